// round 2
// baseline (speedup 1.0000x reference)
#include <cuda_runtime.h>
#include <cstdint>

#define SEQ  2048
#define DM   1024
#define NH   16
#define HDIM 64
#define FFD  4096

// ---------------- scratch (no allocations allowed) ----------------
__device__ float g_Q[NH * SEQ * HDIM];
__device__ float g_K[NH * SEQ * HDIM];
__device__ float g_V[NH * SEQ * HDIM];
__device__ float g_attn[(size_t)NH * SEQ * SEQ];
__device__ float g_concat[SEQ * DM];
__device__ float g_proj[SEQ * DM];
__device__ float g_hidden[SEQ * FFD];

// ---------------- helpers ----------------
__device__ __forceinline__ void split_tf32(float a, float& h, float& l) {
    uint32_t hb;
    asm("cvt.rna.tf32.f32 %0, %1;" : "=r"(hb) : "f"(a));
    h = __uint_as_float(hb);
    float r = a - h;
    uint32_t lb;
    asm("cvt.rna.tf32.f32 %0, %1;" : "=r"(lb) : "f"(r));
    l = __uint_as_float(lb);
}

__device__ __forceinline__ void mma_tf32(float c[4], const uint32_t a[4], const uint32_t b[2]) {
    asm volatile(
        "mma.sync.aligned.m16n8k8.row.col.f32.tf32.tf32.f32 "
        "{%0,%1,%2,%3}, {%4,%5,%6,%7}, {%8,%9}, {%0,%1,%2,%3};"
        : "+f"(c[0]), "+f"(c[1]), "+f"(c[2]), "+f"(c[3])
        : "r"(a[0]), "r"(a[1]), "r"(a[2]), "r"(a[3]), "r"(b[0]), "r"(b[1]));
}

// =====================================================================
// 3xTF32 tensor-core GEMM.  CTA tile 128(M) x 64(N) x 32(K), 256 threads,
// 8 warps in 4(M) x 2(N), warp tile 32x32 -> 2x4 m16n8k8 mmas.
// Layout flags:
//   A_T=0: A[m*lda+k]   A_T=1: A[k*lda+m]
//   B_T=0: B[k*ldb+n]   B_T=1: B[n*ldb+k]
// C[m*ldc+n] (+z*cZ), optional bias/relu/scale.
// smem: hi/lo split tiles, double buffered, padded (A:+8, B:+8).
// =====================================================================
#define SA 136   // 128 + 8
#define SB 72    // 64 + 8
#define MM3_SMEM ((2*2*32*SA + 2*2*32*SB) * 4)

template <int A_T, int B_T, int HAS_BIAS, int RELU, int HAS_SCALE>
__global__ void __launch_bounds__(256, 2)
mm3(const float* __restrict__ A, const float* __restrict__ B,
    const float* __restrict__ bias, float* __restrict__ C,
    int K, int lda, int ldb, int ldc,
    size_t aZ, size_t bZ, size_t cZ, int biasZ, float scale)
{
    extern __shared__ float sm[];
    float* AsBase = sm;                    // [buf][hi/lo][32][SA]
    float* BsBase = sm + 2 * 2 * 32 * SA;  // [buf][hi/lo][32][SB]

    const int tid = threadIdx.x;
    const int z = blockIdx.z;
    A += (size_t)z * aZ;
    B += (size_t)z * bZ;
    C += (size_t)z * cZ;
    const float* biasp = HAS_BIAS ? (bias + (size_t)z * biasZ) : bias;

    const int bm = blockIdx.y * 128;
    const int bn = blockIdx.x * 64;

    const int warp = tid >> 5, lane = tid & 31;
    const int g = lane >> 2, tg = lane & 3;
    const int m0 = (warp & 3) * 32, n0 = (warp >> 2) * 32;

    float ra[16], rb[8];

    auto loadA = [&](int k0) {
        #pragma unroll
        for (int i = 0; i < 4; i++) {
            int f = tid + i * 256;
            if (A_T == 0) {
                int m = f >> 3, kc = (f & 7) << 2;
                *(float4*)&ra[i * 4] = *(const float4*)(A + (size_t)(bm + m) * lda + k0 + kc);
            } else {
                int k = f >> 5, mc = (f & 31) << 2;
                *(float4*)&ra[i * 4] = *(const float4*)(A + (size_t)(k0 + k) * lda + bm + mc);
            }
        }
    };
    auto loadB = [&](int k0) {
        #pragma unroll
        for (int i = 0; i < 2; i++) {
            int f = tid + i * 256;
            if (B_T == 0) {
                int k = f >> 4, nc = (f & 15) << 2;
                *(float4*)&rb[i * 4] = *(const float4*)(B + (size_t)(k0 + k) * ldb + bn + nc);
            } else {
                int n = f >> 3, kc = (f & 7) << 2;
                *(float4*)&rb[i * 4] = *(const float4*)(B + (size_t)(bn + n) * ldb + k0 + kc);
            }
        }
    };
    auto storeA = [&](int buf) {
        float* Ah = AsBase + (buf * 2 + 0) * 32 * SA;
        float* Al = AsBase + (buf * 2 + 1) * 32 * SA;
        #pragma unroll
        for (int i = 0; i < 4; i++) {
            int f = tid + i * 256;
            if (A_T == 0) {
                int m = f >> 3, kc = (f & 7) << 2;
                #pragma unroll
                for (int j = 0; j < 4; j++) {
                    float h, l;
                    split_tf32(ra[i * 4 + j], h, l);
                    Ah[(kc + j) * SA + m] = h;
                    Al[(kc + j) * SA + m] = l;
                }
            } else {
                int k = f >> 5, mc = (f & 31) << 2;
                float4 h4, l4;
                split_tf32(ra[i * 4 + 0], h4.x, l4.x);
                split_tf32(ra[i * 4 + 1], h4.y, l4.y);
                split_tf32(ra[i * 4 + 2], h4.z, l4.z);
                split_tf32(ra[i * 4 + 3], h4.w, l4.w);
                *(float4*)&Ah[k * SA + mc] = h4;
                *(float4*)&Al[k * SA + mc] = l4;
            }
        }
    };
    auto storeB = [&](int buf) {
        float* Bh = BsBase + (buf * 2 + 0) * 32 * SB;
        float* Bl = BsBase + (buf * 2 + 1) * 32 * SB;
        #pragma unroll
        for (int i = 0; i < 2; i++) {
            int f = tid + i * 256;
            if (B_T == 0) {
                int k = f >> 4, nc = (f & 15) << 2;
                float4 h4, l4;
                split_tf32(rb[i * 4 + 0], h4.x, l4.x);
                split_tf32(rb[i * 4 + 1], h4.y, l4.y);
                split_tf32(rb[i * 4 + 2], h4.z, l4.z);
                split_tf32(rb[i * 4 + 3], h4.w, l4.w);
                *(float4*)&Bh[k * SB + nc] = h4;
                *(float4*)&Bl[k * SB + nc] = l4;
            } else {
                int n = f >> 3, kc = (f & 7) << 2;
                #pragma unroll
                for (int j = 0; j < 4; j++) {
                    float h, l;
                    split_tf32(rb[i * 4 + j], h, l);
                    Bh[(kc + j) * SB + n] = h;
                    Bl[(kc + j) * SB + n] = l;
                }
            }
        }
    };

    float acc[2][4][4];
    #pragma unroll
    for (int tm = 0; tm < 2; tm++)
        #pragma unroll
        for (int tn = 0; tn < 4; tn++)
            #pragma unroll
            for (int r = 0; r < 4; r++) acc[tm][tn][r] = 0.f;

    const int nk = K >> 5;

    loadA(0); loadB(0);
    storeA(0); storeB(0);
    __syncthreads();

    for (int kt = 0; kt < nk; kt++) {
        const int cur = kt & 1;
        if (kt + 1 < nk) { loadA((kt + 1) << 5); loadB((kt + 1) << 5); }

        const float* Ah = AsBase + (cur * 2 + 0) * 32 * SA;
        const float* Al = AsBase + (cur * 2 + 1) * 32 * SA;
        const float* Bh = BsBase + (cur * 2 + 0) * 32 * SB;
        const float* Bl = BsBase + (cur * 2 + 1) * 32 * SB;

        #pragma unroll
        for (int ks = 0; ks < 4; ks++) {
            const int kb = ks * 8;
            uint32_t ah[2][4], al[2][4], bh[4][2], bl[4][2];
            #pragma unroll
            for (int tm = 0; tm < 2; tm++) {
                const int mm = m0 + tm * 16 + g;
                ah[tm][0] = __float_as_uint(Ah[(kb + tg) * SA + mm]);
                ah[tm][1] = __float_as_uint(Ah[(kb + tg) * SA + mm + 8]);
                ah[tm][2] = __float_as_uint(Ah[(kb + tg + 4) * SA + mm]);
                ah[tm][3] = __float_as_uint(Ah[(kb + tg + 4) * SA + mm + 8]);
                al[tm][0] = __float_as_uint(Al[(kb + tg) * SA + mm]);
                al[tm][1] = __float_as_uint(Al[(kb + tg) * SA + mm + 8]);
                al[tm][2] = __float_as_uint(Al[(kb + tg + 4) * SA + mm]);
                al[tm][3] = __float_as_uint(Al[(kb + tg + 4) * SA + mm + 8]);
            }
            #pragma unroll
            for (int tn = 0; tn < 4; tn++) {
                const int nn = n0 + tn * 8 + g;
                bh[tn][0] = __float_as_uint(Bh[(kb + tg) * SB + nn]);
                bh[tn][1] = __float_as_uint(Bh[(kb + tg + 4) * SB + nn]);
                bl[tn][0] = __float_as_uint(Bl[(kb + tg) * SB + nn]);
                bl[tn][1] = __float_as_uint(Bl[(kb + tg + 4) * SB + nn]);
            }
            #pragma unroll
            for (int tm = 0; tm < 2; tm++)
                #pragma unroll
                for (int tn = 0; tn < 4; tn++) {
                    mma_tf32(acc[tm][tn], ah[tm], bh[tn]);
                    mma_tf32(acc[tm][tn], ah[tm], bl[tn]);
                    mma_tf32(acc[tm][tn], al[tm], bh[tn]);
                }
        }

        if (kt + 1 < nk) { storeA(cur ^ 1); storeB(cur ^ 1); }
        __syncthreads();
    }

    // epilogue
    #pragma unroll
    for (int tm = 0; tm < 2; tm++) {
        #pragma unroll
        for (int tn = 0; tn < 4; tn++) {
            const int col = bn + n0 + tn * 8 + 2 * tg;
            float2 bb = make_float2(0.f, 0.f);
            if (HAS_BIAS) bb = *(const float2*)(biasp + col);
            #pragma unroll
            for (int half = 0; half < 2; half++) {
                const int row = bm + m0 + tm * 16 + g + half * 8;
                float2 v;
                v.x = acc[tm][tn][half * 2 + 0];
                v.y = acc[tm][tn][half * 2 + 1];
                if (HAS_SCALE) { v.x *= scale; v.y *= scale; }
                if (HAS_BIAS)  { v.x += bb.x;  v.y += bb.y;  }
                if (RELU)      { v.x = fmaxf(v.x, 0.f); v.y = fmaxf(v.y, 0.f); }
                *(float2*)(C + (size_t)row * ldc + col) = v;
            }
        }
    }
}

// =====================================================================
// Row softmax over t: NH*SEQ rows of length SEQ, in place.
// =====================================================================
__global__ __launch_bounds__(256)
void softmax_kernel(float* __restrict__ attn)
{
    __shared__ float red[8];
    float* p = attn + (size_t)blockIdx.x * SEQ;
    const int t = threadIdx.x;
    const int lane = t & 31, warp = t >> 5;

    float v[8];
    #pragma unroll
    for (int i = 0; i < 8; i++) v[i] = p[t + i * 256];

    float m = v[0];
    #pragma unroll
    for (int i = 1; i < 8; i++) m = fmaxf(m, v[i]);
    #pragma unroll
    for (int o = 16; o > 0; o >>= 1) m = fmaxf(m, __shfl_xor_sync(0xffffffffu, m, o));
    if (lane == 0) red[warp] = m;
    __syncthreads();
    float mm = red[0];
    #pragma unroll
    for (int i = 1; i < 8; i++) mm = fmaxf(mm, red[i]);
    __syncthreads();

    float s = 0.f;
    #pragma unroll
    for (int i = 0; i < 8; i++) { v[i] = __expf(v[i] - mm); s += v[i]; }
    #pragma unroll
    for (int o = 16; o > 0; o >>= 1) s += __shfl_xor_sync(0xffffffffu, s, o);
    if (lane == 0) red[warp] = s;
    __syncthreads();
    float ss = 0.f;
    #pragma unroll
    for (int i = 0; i < 8; i++) ss += red[i];
    const float inv = 1.f / ss;

    #pragma unroll
    for (int i = 0; i < 8; i++) p[t + i * 256] = v[i] * inv;
}

// =====================================================================
extern "C" void kernel_launch(void* const* d_in, const int* in_sizes, int n_in,
                              void* d_out, int out_size)
{
    const float* x  = (const float*)d_in[0];
    const float* Wq = (const float*)d_in[1];
    const float* bq = (const float*)d_in[2];
    const float* Wk = (const float*)d_in[3];
    const float* bk = (const float*)d_in[4];
    const float* Wv = (const float*)d_in[5];
    const float* bv = (const float*)d_in[6];
    const float* Wp = (const float*)d_in[7];
    const float* bp = (const float*)d_in[8];
    const float* W1 = (const float*)d_in[9];
    const float* b1 = (const float*)d_in[10];
    const float* W2 = (const float*)d_in[11];
    const float* b2 = (const float*)d_in[12];
    float* out = (float*)d_out;

    float *Q, *K, *V, *attn, *concat, *proj, *hidden;
    cudaGetSymbolAddress((void**)&Q,      g_Q);
    cudaGetSymbolAddress((void**)&K,      g_K);
    cudaGetSymbolAddress((void**)&V,      g_V);
    cudaGetSymbolAddress((void**)&attn,   g_attn);
    cudaGetSymbolAddress((void**)&concat, g_concat);
    cudaGetSymbolAddress((void**)&proj,   g_proj);
    cudaGetSymbolAddress((void**)&hidden, g_hidden);

    // opt-in to >48KB dynamic smem (host-side attribute, not a stream op)
    cudaFuncSetAttribute(mm3<0,0,1,0,0>, cudaFuncAttributeMaxDynamicSharedMemorySize, MM3_SMEM);
    cudaFuncSetAttribute(mm3<0,1,0,0,1>, cudaFuncAttributeMaxDynamicSharedMemorySize, MM3_SMEM);
    cudaFuncSetAttribute(mm3<1,0,0,0,0>, cudaFuncAttributeMaxDynamicSharedMemorySize, MM3_SMEM);
    cudaFuncSetAttribute(mm3<0,0,1,1,0>, cudaFuncAttributeMaxDynamicSharedMemorySize, MM3_SMEM);

    // 1) QKV: per-head NN gemm, z = head. A=x[2048,1024]; B=W[h][1024,64]; C=[h][2048,64]
    {
        dim3 grid(1, SEQ / 128, NH);
        mm3<0,0,1,0,0><<<grid, 256, MM3_SMEM>>>(x, Wq, bq, Q, DM, DM, HDIM, HDIM,
                                                0, (size_t)DM * HDIM, (size_t)SEQ * HDIM, HDIM, 1.f);
        mm3<0,0,1,0,0><<<grid, 256, MM3_SMEM>>>(x, Wk, bk, K, DM, DM, HDIM, HDIM,
                                                0, (size_t)DM * HDIM, (size_t)SEQ * HDIM, HDIM, 1.f);
        mm3<0,0,1,0,0><<<grid, 256, MM3_SMEM>>>(x, Wv, bv, V, DM, DM, HDIM, HDIM,
                                                0, (size_t)DM * HDIM, (size_t)SEQ * HDIM, HDIM, 1.f);
    }

    // 2) scores[h,s,t] = Q[h,s,:].K[h,t,:] / 8   (B transposed)
    {
        dim3 grid(SEQ / 64, SEQ / 128, NH);
        mm3<0,1,0,0,1><<<grid, 256, MM3_SMEM>>>(Q, K, nullptr, attn, HDIM, HDIM, HDIM, SEQ,
                                                (size_t)SEQ * HDIM, (size_t)SEQ * HDIM,
                                                (size_t)SEQ * SEQ, 0, 0.125f);
    }

    // 3) softmax over t
    softmax_kernel<<<NH * SEQ, 256>>>(attn);

    // 4) concat[t, h*64+e] = sum_s attn[h,s,t] V[h,s,e]   (A stored k-major)
    {
        dim3 grid(1, SEQ / 128, NH);
        mm3<1,0,0,0,0><<<grid, 256, MM3_SMEM>>>(attn, V, nullptr, concat, SEQ, SEQ, HDIM, DM,
                                                (size_t)SEQ * SEQ, (size_t)SEQ * HDIM,
                                                (size_t)HDIM, 0, 1.f);
    }

    // 5) proj = concat @ Wp + bp
    mm3<0,0,1,0,0><<<dim3(DM / 64, SEQ / 128, 1), 256, MM3_SMEM>>>(
        concat, Wp, bp, proj, DM, DM, DM, DM, 0, 0, 0, 0, 1.f);

    // 6) hidden = relu(proj @ W1 + b1)
    mm3<0,0,1,1,0><<<dim3(FFD / 64, SEQ / 128, 1), 256, MM3_SMEM>>>(
        proj, W1, b1, hidden, DM, DM, FFD, FFD, 0, 0, 0, 0, 1.f);

    // 7) out = hidden @ W2 + b2
    mm3<0,0,1,0,0><<<dim3(DM / 64, SEQ / 128, 1), 256, MM3_SMEM>>>(
        hidden, W2, b2, out, FFD, FFD, DM, DM, 0, 0, 0, 0, 1.f);
}

// round 3
// speedup vs baseline: 2.5531x; 2.5531x over previous
#include <cuda_runtime.h>
#include <cuda_bf16.h>
#include <cstdint>

#define SEQ  2048
#define DM   1024
#define NH   16
#define HDIM 64
#define FFD  4096

// ---------------- scratch (no allocations allowed) ----------------
__device__ float g_Q[NH * SEQ * HDIM];
__device__ float g_K[NH * SEQ * HDIM];
__device__ float g_V[NH * SEQ * HDIM];
__device__ float g_attn[(size_t)NH * SEQ * SEQ];
__device__ float g_concat[SEQ * DM];
__device__ float g_proj[SEQ * DM];
__device__ float g_hidden[SEQ * FFD];

// ---------------- helpers ----------------
__device__ __forceinline__ void split_bf16(float a, __nv_bfloat16& h, __nv_bfloat16& l) {
    h = __float2bfloat16_rn(a);
    l = __float2bfloat16_rn(a - __bfloat162float(h));
}
__device__ __forceinline__ uint32_t pk(__nv_bfloat16 a, __nv_bfloat16 b) {
    __nv_bfloat162 t(a, b);
    return *reinterpret_cast<uint32_t*>(&t);
}
__device__ __forceinline__ void ldsm4(uint32_t& r0, uint32_t& r1, uint32_t& r2, uint32_t& r3, uint32_t addr) {
    asm volatile("ldmatrix.sync.aligned.m8n8.x4.shared.b16 {%0,%1,%2,%3}, [%4];"
                 : "=r"(r0), "=r"(r1), "=r"(r2), "=r"(r3) : "r"(addr));
}
__device__ __forceinline__ void ldsm4t(uint32_t& r0, uint32_t& r1, uint32_t& r2, uint32_t& r3, uint32_t addr) {
    asm volatile("ldmatrix.sync.aligned.m8n8.x4.trans.shared.b16 {%0,%1,%2,%3}, [%4];"
                 : "=r"(r0), "=r"(r1), "=r"(r2), "=r"(r3) : "r"(addr));
}
__device__ __forceinline__ void mma_bf16(float c[4], const uint32_t a[4], const uint32_t b[2]) {
    asm volatile(
        "mma.sync.aligned.m16n8k16.row.col.f32.bf16.bf16.f32 "
        "{%0,%1,%2,%3}, {%4,%5,%6,%7}, {%8,%9}, {%0,%1,%2,%3};"
        : "+f"(c[0]), "+f"(c[1]), "+f"(c[2]), "+f"(c[3])
        : "r"(a[0]), "r"(a[1]), "r"(a[2]), "r"(a[3]), "r"(b[0]), "r"(b[1]));
}

// =====================================================================
// bf16 split-2 tensor-core GEMM. CTA 128(M) x 64(N) x 32(K), 256 thr,
// warps 4(m) x 2(n), warp tile 32x32: 2 m-blk x 4 n-blk m16n8k16 mmas.
// Layouts:
//   A_T=0: A[m*lda+k] -> smem [m][pitch 40], LDSM non-trans
//   A_T=1: A[k*lda+m] -> smem [k][pitch 136], LDSM trans
//   B_T=0: B[k*ldb+n] -> smem [k][pitch 72],  LDSM trans
//   B_T=1: B[n*ldb+k] -> smem [n][pitch 40],  LDSM non-trans
// smem per (buf,half): A seg 10240 B, B seg 5120 B; x hi/lo x 2 buf.
// =====================================================================
#define A_SEG 10240
#define B_SEG 5120
#define MMBF_SMEM (4 * A_SEG + 4 * B_SEG)   // 61440 B

template <int A_T, int B_T, int HAS_BIAS, int RELU, int HAS_SCALE>
__global__ void __launch_bounds__(256, 2)
mmbf(const float* __restrict__ A, const float* __restrict__ B,
     const float* __restrict__ bias, float* __restrict__ C,
     int K, int lda, int ldb, int ldc,
     size_t aZ, size_t bZ, size_t cZ, int biasZ, float scale)
{
    extern __shared__ __align__(16) unsigned char smraw[];
    const uint32_t smBase = (uint32_t)__cvta_generic_to_shared(smraw);

    const int tid = threadIdx.x;
    const int z = blockIdx.z;
    A += (size_t)z * aZ;
    B += (size_t)z * bZ;
    C += (size_t)z * cZ;
    const float* biasp = HAS_BIAS ? (bias + (size_t)z * biasZ) : bias;

    const int bm = blockIdx.y * 128;
    const int bn = blockIdx.x * 64;

    const int warp = tid >> 5, lane = tid & 31;
    const int g = lane >> 2, tg = lane & 3;
    const int m0 = (warp & 3) * 32, n0 = (warp >> 2) * 32;
    const int b3 = (lane >> 3) & 1, b4 = (lane >> 4) & 1;

    // ---- LDSM lane offsets (bytes, within a (buf,half) segment) ----
    uint32_t aOff[2], bOff[2];
    #pragma unroll
    for (int tm = 0; tm < 2; tm++) {
        if (A_T == 0)
            aOff[tm] = ((m0 + tm * 16 + (lane & 7) + b3 * 8) * 40 + b4 * 8) * 2;
        else
            aOff[tm] = (((lane & 7) + b4 * 8) * 136 + m0 + tm * 16 + b3 * 8) * 2;
    }
    #pragma unroll
    for (int p = 0; p < 2; p++) {
        if (B_T == 0)
            bOff[p] = (((lane & 7) + b3 * 8) * 72 + n0 + p * 16 + b4 * 8) * 2;
        else
            bOff[p] = ((n0 + p * 16 + (lane & 7) + b4 * 8) * 40 + b3 * 8) * 2;
    }
    const uint32_t aStep = (A_T == 0) ? 32u : 4352u;   // per 16-k step, bytes
    const uint32_t bStep = (B_T == 0) ? 2304u : 32u;

    float ra[16], rb[8];

    auto loadA = [&](int k0) {
        #pragma unroll
        for (int i = 0; i < 4; i++) {
            int f = tid + i * 256;
            if (A_T == 0) {
                int m = f >> 3, kc = (f & 7) << 2;
                *(float4*)&ra[i * 4] = *(const float4*)(A + (size_t)(bm + m) * lda + k0 + kc);
            } else {
                int k = f >> 5, mc = (f & 31) << 2;
                *(float4*)&ra[i * 4] = *(const float4*)(A + (size_t)(k0 + k) * lda + bm + mc);
            }
        }
    };
    auto loadB = [&](int k0) {
        #pragma unroll
        for (int i = 0; i < 2; i++) {
            int f = tid + i * 256;
            if (B_T == 0) {
                int k = f >> 4, nc = (f & 15) << 2;
                *(float4*)&rb[i * 4] = *(const float4*)(B + (size_t)(k0 + k) * ldb + bn + nc);
            } else {
                int n = f >> 3, kc = (f & 7) << 2;
                *(float4*)&rb[i * 4] = *(const float4*)(B + (size_t)(bn + n) * ldb + k0 + kc);
            }
        }
    };
    auto storeA = [&](int buf) {
        __nv_bfloat16* Ah = (__nv_bfloat16*)(smraw + (buf * 2 + 0) * A_SEG);
        __nv_bfloat16* Al = (__nv_bfloat16*)(smraw + (buf * 2 + 1) * A_SEG);
        #pragma unroll
        for (int i = 0; i < 4; i++) {
            int f = tid + i * 256;
            __nv_bfloat16 h[4], l[4];
            #pragma unroll
            for (int j = 0; j < 4; j++) split_bf16(ra[i * 4 + j], h[j], l[j]);
            uint2 H = make_uint2(pk(h[0], h[1]), pk(h[2], h[3]));
            uint2 L = make_uint2(pk(l[0], l[1]), pk(l[2], l[3]));
            if (A_T == 0) {
                int m = f >> 3, kc = (f & 7) << 2;
                *(uint2*)&Ah[m * 40 + kc] = H;
                *(uint2*)&Al[m * 40 + kc] = L;
            } else {
                int k = f >> 5, mc = (f & 31) << 2;
                *(uint2*)&Ah[k * 136 + mc] = H;
                *(uint2*)&Al[k * 136 + mc] = L;
            }
        }
    };
    auto storeB = [&](int buf) {
        __nv_bfloat16* Bh = (__nv_bfloat16*)(smraw + 4 * A_SEG + (buf * 2 + 0) * B_SEG);
        __nv_bfloat16* Bl = (__nv_bfloat16*)(smraw + 4 * A_SEG + (buf * 2 + 1) * B_SEG);
        #pragma unroll
        for (int i = 0; i < 2; i++) {
            int f = tid + i * 256;
            __nv_bfloat16 h[4], l[4];
            #pragma unroll
            for (int j = 0; j < 4; j++) split_bf16(rb[i * 4 + j], h[j], l[j]);
            uint2 H = make_uint2(pk(h[0], h[1]), pk(h[2], h[3]));
            uint2 L = make_uint2(pk(l[0], l[1]), pk(l[2], l[3]));
            if (B_T == 0) {
                int k = f >> 4, nc = (f & 15) << 2;
                *(uint2*)&Bh[k * 72 + nc] = H;
                *(uint2*)&Bl[k * 72 + nc] = L;
            } else {
                int n = f >> 3, kc = (f & 7) << 2;
                *(uint2*)&Bh[n * 40 + kc] = H;
                *(uint2*)&Bl[n * 40 + kc] = L;
            }
        }
    };

    float acc[2][4][4];
    #pragma unroll
    for (int tm = 0; tm < 2; tm++)
        #pragma unroll
        for (int tn = 0; tn < 4; tn++)
            #pragma unroll
            for (int r = 0; r < 4; r++) acc[tm][tn][r] = 0.f;

    const int nk = K >> 5;

    loadA(0); loadB(0);
    storeA(0); storeB(0);
    __syncthreads();

    for (int kt = 0; kt < nk; kt++) {
        const int cur = kt & 1;
        if (kt + 1 < nk) { loadA((kt + 1) << 5); loadB((kt + 1) << 5); }

        const uint32_t AhB = smBase + (cur * 2 + 0) * A_SEG;
        const uint32_t AlB = smBase + (cur * 2 + 1) * A_SEG;
        const uint32_t BhB = smBase + 4 * A_SEG + (cur * 2 + 0) * B_SEG;
        const uint32_t BlB = smBase + 4 * A_SEG + (cur * 2 + 1) * B_SEG;

        #pragma unroll
        for (int ks = 0; ks < 2; ks++) {
            uint32_t ah[2][4], al[2][4], bh[4][2], bl[4][2];
            #pragma unroll
            for (int tm = 0; tm < 2; tm++) {
                if (A_T == 0) {
                    ldsm4(ah[tm][0], ah[tm][1], ah[tm][2], ah[tm][3], AhB + aOff[tm] + ks * aStep);
                    ldsm4(al[tm][0], al[tm][1], al[tm][2], al[tm][3], AlB + aOff[tm] + ks * aStep);
                } else {
                    ldsm4t(ah[tm][0], ah[tm][1], ah[tm][2], ah[tm][3], AhB + aOff[tm] + ks * aStep);
                    ldsm4t(al[tm][0], al[tm][1], al[tm][2], al[tm][3], AlB + aOff[tm] + ks * aStep);
                }
            }
            #pragma unroll
            for (int p = 0; p < 2; p++) {
                uint32_t r0, r1, r2, r3;
                if (B_T == 0) ldsm4t(r0, r1, r2, r3, BhB + bOff[p] + ks * bStep);
                else          ldsm4 (r0, r1, r2, r3, BhB + bOff[p] + ks * bStep);
                bh[p * 2 + 0][0] = r0; bh[p * 2 + 0][1] = r1;
                bh[p * 2 + 1][0] = r2; bh[p * 2 + 1][1] = r3;
                if (B_T == 0) ldsm4t(r0, r1, r2, r3, BlB + bOff[p] + ks * bStep);
                else          ldsm4 (r0, r1, r2, r3, BlB + bOff[p] + ks * bStep);
                bl[p * 2 + 0][0] = r0; bl[p * 2 + 0][1] = r1;
                bl[p * 2 + 1][0] = r2; bl[p * 2 + 1][1] = r3;
            }
            #pragma unroll
            for (int tm = 0; tm < 2; tm++)
                #pragma unroll
                for (int tn = 0; tn < 4; tn++) {
                    mma_bf16(acc[tm][tn], ah[tm], bh[tn]);
                    mma_bf16(acc[tm][tn], ah[tm], bl[tn]);
                    mma_bf16(acc[tm][tn], al[tm], bh[tn]);
                }
        }

        if (kt + 1 < nk) { storeA(cur ^ 1); storeB(cur ^ 1); }
        __syncthreads();
    }

    // ---- epilogue ----
    #pragma unroll
    for (int tm = 0; tm < 2; tm++) {
        #pragma unroll
        for (int tn = 0; tn < 4; tn++) {
            const int col = bn + n0 + tn * 8 + 2 * tg;
            float2 bb = make_float2(0.f, 0.f);
            if (HAS_BIAS) bb = *(const float2*)(biasp + col);
            #pragma unroll
            for (int half = 0; half < 2; half++) {
                const int row = bm + m0 + tm * 16 + g + half * 8;
                float2 v;
                v.x = acc[tm][tn][half * 2 + 0];
                v.y = acc[tm][tn][half * 2 + 1];
                if (HAS_SCALE) { v.x *= scale; v.y *= scale; }
                if (HAS_BIAS)  { v.x += bb.x;  v.y += bb.y;  }
                if (RELU)      { v.x = fmaxf(v.x, 0.f); v.y = fmaxf(v.y, 0.f); }
                *(float2*)(C + (size_t)row * ldc + col) = v;
            }
        }
    }
}

// =====================================================================
// Row softmax over t: NH*SEQ rows of length SEQ, in place.
// =====================================================================
__global__ __launch_bounds__(256)
void softmax_kernel(float* __restrict__ attn)
{
    __shared__ float red[8];
    float* p = attn + (size_t)blockIdx.x * SEQ;
    const int t = threadIdx.x;
    const int lane = t & 31, warp = t >> 5;

    float v[8];
    #pragma unroll
    for (int i = 0; i < 8; i++) v[i] = p[t + i * 256];

    float m = v[0];
    #pragma unroll
    for (int i = 1; i < 8; i++) m = fmaxf(m, v[i]);
    #pragma unroll
    for (int o = 16; o > 0; o >>= 1) m = fmaxf(m, __shfl_xor_sync(0xffffffffu, m, o));
    if (lane == 0) red[warp] = m;
    __syncthreads();
    float mm = red[0];
    #pragma unroll
    for (int i = 1; i < 8; i++) mm = fmaxf(mm, red[i]);
    __syncthreads();

    float s = 0.f;
    #pragma unroll
    for (int i = 0; i < 8; i++) { v[i] = __expf(v[i] - mm); s += v[i]; }
    #pragma unroll
    for (int o = 16; o > 0; o >>= 1) s += __shfl_xor_sync(0xffffffffu, s, o);
    if (lane == 0) red[warp] = s;
    __syncthreads();
    float ss = 0.f;
    #pragma unroll
    for (int i = 0; i < 8; i++) ss += red[i];
    const float inv = 1.f / ss;

    #pragma unroll
    for (int i = 0; i < 8; i++) p[t + i * 256] = v[i] * inv;
}

// =====================================================================
extern "C" void kernel_launch(void* const* d_in, const int* in_sizes, int n_in,
                              void* d_out, int out_size)
{
    const float* x  = (const float*)d_in[0];
    const float* Wq = (const float*)d_in[1];
    const float* bq = (const float*)d_in[2];
    const float* Wk = (const float*)d_in[3];
    const float* bk = (const float*)d_in[4];
    const float* Wv = (const float*)d_in[5];
    const float* bv = (const float*)d_in[6];
    const float* Wp = (const float*)d_in[7];
    const float* bp = (const float*)d_in[8];
    const float* W1 = (const float*)d_in[9];
    const float* b1 = (const float*)d_in[10];
    const float* W2 = (const float*)d_in[11];
    const float* b2 = (const float*)d_in[12];
    float* out = (float*)d_out;

    float *Q, *K, *V, *attn, *concat, *proj, *hidden;
    cudaGetSymbolAddress((void**)&Q,      g_Q);
    cudaGetSymbolAddress((void**)&K,      g_K);
    cudaGetSymbolAddress((void**)&V,      g_V);
    cudaGetSymbolAddress((void**)&attn,   g_attn);
    cudaGetSymbolAddress((void**)&concat, g_concat);
    cudaGetSymbolAddress((void**)&proj,   g_proj);
    cudaGetSymbolAddress((void**)&hidden, g_hidden);

    cudaFuncSetAttribute(mmbf<0,0,1,0,0>, cudaFuncAttributeMaxDynamicSharedMemorySize, MMBF_SMEM);
    cudaFuncSetAttribute(mmbf<0,1,0,0,1>, cudaFuncAttributeMaxDynamicSharedMemorySize, MMBF_SMEM);
    cudaFuncSetAttribute(mmbf<1,0,0,0,0>, cudaFuncAttributeMaxDynamicSharedMemorySize, MMBF_SMEM);
    cudaFuncSetAttribute(mmbf<0,0,1,1,0>, cudaFuncAttributeMaxDynamicSharedMemorySize, MMBF_SMEM);

    // 1) QKV: per-head NN gemm, z = head
    {
        dim3 grid(1, SEQ / 128, NH);
        mmbf<0,0,1,0,0><<<grid, 256, MMBF_SMEM>>>(x, Wq, bq, Q, DM, DM, HDIM, HDIM,
                                                  0, (size_t)DM * HDIM, (size_t)SEQ * HDIM, HDIM, 1.f);
        mmbf<0,0,1,0,0><<<grid, 256, MMBF_SMEM>>>(x, Wk, bk, K, DM, DM, HDIM, HDIM,
                                                  0, (size_t)DM * HDIM, (size_t)SEQ * HDIM, HDIM, 1.f);
        mmbf<0,0,1,0,0><<<grid, 256, MMBF_SMEM>>>(x, Wv, bv, V, DM, DM, HDIM, HDIM,
                                                  0, (size_t)DM * HDIM, (size_t)SEQ * HDIM, HDIM, 1.f);
    }

    // 2) scores[h,s,t] = Q[h,s,:].K[h,t,:] / 8  (B transposed)
    {
        dim3 grid(SEQ / 64, SEQ / 128, NH);
        mmbf<0,1,0,0,1><<<grid, 256, MMBF_SMEM>>>(Q, K, nullptr, attn, HDIM, HDIM, HDIM, SEQ,
                                                  (size_t)SEQ * HDIM, (size_t)SEQ * HDIM,
                                                  (size_t)SEQ * SEQ, 0, 0.125f);
    }

    // 3) softmax over t
    softmax_kernel<<<NH * SEQ, 256>>>(attn);

    // 4) concat[t, h*64+e] = sum_s attn[h,s,t] V[h,s,e]  (A stored k-major)
    {
        dim3 grid(1, SEQ / 128, NH);
        mmbf<1,0,0,0,0><<<grid, 256, MMBF_SMEM>>>(attn, V, nullptr, concat, SEQ, SEQ, HDIM, DM,
                                                  (size_t)SEQ * SEQ, (size_t)SEQ * HDIM,
                                                  (size_t)HDIM, 0, 1.f);
    }

    // 5) proj = concat @ Wp + bp
    mmbf<0,0,1,0,0><<<dim3(DM / 64, SEQ / 128, 1), 256, MMBF_SMEM>>>(
        concat, Wp, bp, proj, DM, DM, DM, DM, 0, 0, 0, 0, 1.f);

    // 6) hidden = relu(proj @ W1 + b1)
    mmbf<0,0,1,1,0><<<dim3(FFD / 64, SEQ / 128, 1), 256, MMBF_SMEM>>>(
        proj, W1, b1, hidden, DM, DM, FFD, FFD, 0, 0, 0, 0, 1.f);

    // 7) out = hidden @ W2 + b2
    mmbf<0,0,1,0,0><<<dim3(DM / 64, SEQ / 128, 1), 256, MMBF_SMEM>>>(
        hidden, W2, b2, out, FFD, FFD, DM, DM, 0, 0, 0, 0, 1.f);
}

// round 4
// speedup vs baseline: 2.6863x; 1.0522x over previous
#include <cuda_runtime.h>
#include <cuda_bf16.h>
#include <cstdint>

#define SEQ  2048
#define DM   1024
#define NH   16
#define HDIM 64
#define FFD  4096

// ---------------- scratch (no allocations allowed) ----------------
__device__ float g_Q[NH * SEQ * HDIM];
__device__ float g_K[NH * SEQ * HDIM];
__device__ float g_V[NH * SEQ * HDIM];
__device__ float g_attn[(size_t)NH * SEQ * SEQ];   // holds exp(scores/8)
__device__ float g_Z[NH * SEQ];                    // per-row sums of exp
__device__ float g_concat[SEQ * DM];
__device__ float g_proj[SEQ * DM];
__device__ float g_hidden[SEQ * FFD];

// ---------------- helpers ----------------
__device__ __forceinline__ void split_bf16(float a, __nv_bfloat16& h, __nv_bfloat16& l) {
    h = __float2bfloat16_rn(a);
    l = __float2bfloat16_rn(a - __bfloat162float(h));
}
__device__ __forceinline__ uint32_t pk(__nv_bfloat16 a, __nv_bfloat16 b) {
    __nv_bfloat162 t(a, b);
    return *reinterpret_cast<uint32_t*>(&t);
}
__device__ __forceinline__ void ldsm4(uint32_t& r0, uint32_t& r1, uint32_t& r2, uint32_t& r3, uint32_t addr) {
    asm volatile("ldmatrix.sync.aligned.m8n8.x4.shared.b16 {%0,%1,%2,%3}, [%4];"
                 : "=r"(r0), "=r"(r1), "=r"(r2), "=r"(r3) : "r"(addr));
}
__device__ __forceinline__ void ldsm4t(uint32_t& r0, uint32_t& r1, uint32_t& r2, uint32_t& r3, uint32_t addr) {
    asm volatile("ldmatrix.sync.aligned.m8n8.x4.trans.shared.b16 {%0,%1,%2,%3}, [%4];"
                 : "=r"(r0), "=r"(r1), "=r"(r2), "=r"(r3) : "r"(addr));
}
__device__ __forceinline__ void mma_bf16(float c[4], const uint32_t a[4], const uint32_t b[2]) {
    asm volatile(
        "mma.sync.aligned.m16n8k16.row.col.f32.bf16.bf16.f32 "
        "{%0,%1,%2,%3}, {%4,%5,%6,%7}, {%8,%9}, {%0,%1,%2,%3};"
        : "+f"(c[0]), "+f"(c[1]), "+f"(c[2]), "+f"(c[3])
        : "r"(a[0]), "r"(a[1]), "r"(a[2]), "r"(a[3]), "r"(b[0]), "r"(b[1]));
}

// =====================================================================
// bf16 split-2 tensor-core GEMM. CTA 128(M) x 64(N) x 32(K), 256 thr.
// EXPZ: 0 = plain; 1 = epilogue writes exp(scale*acc), atomically adds
// row-sums into Z; 2 = A operand (A_T=1 path) scaled by 1/Z[k] while
// staging (AV normalization).
// =====================================================================
#define A_SEG 10240
#define B_SEG 5120
#define MMBF_SMEM (4 * A_SEG + 4 * B_SEG)   // 61440 B

template <int A_T, int B_T, int HAS_BIAS, int RELU, int HAS_SCALE, int EXPZ>
__global__ void __launch_bounds__(256, 2)
mmbf(const float* __restrict__ A, const float* __restrict__ B,
     const float* __restrict__ bias, float* __restrict__ C,
     float* __restrict__ Zbuf,
     int K, int lda, int ldb, int ldc,
     size_t aZ, size_t bZ, size_t cZ, int biasZ, float scale)
{
    extern __shared__ __align__(16) unsigned char smraw[];
    const uint32_t smBase = (uint32_t)__cvta_generic_to_shared(smraw);

    const int tid = threadIdx.x;
    const int z = blockIdx.z;
    A += (size_t)z * aZ;
    B += (size_t)z * bZ;
    C += (size_t)z * cZ;
    float* Zp = (EXPZ != 0) ? (Zbuf + (size_t)z * SEQ) : nullptr;
    const float* biasp = HAS_BIAS ? (bias + (size_t)z * biasZ) : bias;

    const int bm = blockIdx.y * 128;
    const int bn = blockIdx.x * 64;

    const int warp = tid >> 5, lane = tid & 31;
    const int g = lane >> 2, tg = lane & 3;
    const int m0 = (warp & 3) * 32, n0 = (warp >> 2) * 32;
    const int b3 = (lane >> 3) & 1, b4 = (lane >> 4) & 1;

    uint32_t aOff[2], bOff[2];
    #pragma unroll
    for (int tm = 0; tm < 2; tm++) {
        if (A_T == 0)
            aOff[tm] = ((m0 + tm * 16 + (lane & 7) + b3 * 8) * 40 + b4 * 8) * 2;
        else
            aOff[tm] = (((lane & 7) + b4 * 8) * 136 + m0 + tm * 16 + b3 * 8) * 2;
    }
    #pragma unroll
    for (int p = 0; p < 2; p++) {
        if (B_T == 0)
            bOff[p] = (((lane & 7) + b3 * 8) * 72 + n0 + p * 16 + b4 * 8) * 2;
        else
            bOff[p] = ((n0 + p * 16 + (lane & 7) + b4 * 8) * 40 + b3 * 8) * 2;
    }
    const uint32_t aStep = (A_T == 0) ? 32u : 4352u;
    const uint32_t bStep = (B_T == 0) ? 2304u : 32u;

    float ra[16], rb[8];
    int kAst = 0;   // k0 of the tile currently staged in ra (for EXPZ==2)

    auto loadA = [&](int k0) {
        kAst = k0;
        #pragma unroll
        for (int i = 0; i < 4; i++) {
            int f = tid + i * 256;
            if (A_T == 0) {
                int m = f >> 3, kc = (f & 7) << 2;
                *(float4*)&ra[i * 4] = *(const float4*)(A + (size_t)(bm + m) * lda + k0 + kc);
            } else {
                int k = f >> 5, mc = (f & 31) << 2;
                *(float4*)&ra[i * 4] = *(const float4*)(A + (size_t)(k0 + k) * lda + bm + mc);
            }
        }
    };
    auto loadB = [&](int k0) {
        #pragma unroll
        for (int i = 0; i < 2; i++) {
            int f = tid + i * 256;
            if (B_T == 0) {
                int k = f >> 4, nc = (f & 15) << 2;
                *(float4*)&rb[i * 4] = *(const float4*)(B + (size_t)(k0 + k) * ldb + bn + nc);
            } else {
                int n = f >> 3, kc = (f & 7) << 2;
                *(float4*)&rb[i * 4] = *(const float4*)(B + (size_t)(bn + n) * ldb + k0 + kc);
            }
        }
    };
    auto storeA = [&](int buf) {
        __nv_bfloat16* Ah = (__nv_bfloat16*)(smraw + (buf * 2 + 0) * A_SEG);
        __nv_bfloat16* Al = (__nv_bfloat16*)(smraw + (buf * 2 + 1) * A_SEG);
        #pragma unroll
        for (int i = 0; i < 4; i++) {
            int f = tid + i * 256;
            float w = 1.f;
            if (EXPZ == 2 && A_T == 1) w = 1.f / Zp[kAst + (f >> 5)];
            __nv_bfloat16 h[4], l[4];
            #pragma unroll
            for (int j = 0; j < 4; j++) {
                float v = ra[i * 4 + j];
                if (EXPZ == 2 && A_T == 1) v *= w;
                split_bf16(v, h[j], l[j]);
            }
            uint2 H = make_uint2(pk(h[0], h[1]), pk(h[2], h[3]));
            uint2 L = make_uint2(pk(l[0], l[1]), pk(l[2], l[3]));
            if (A_T == 0) {
                int m = f >> 3, kc = (f & 7) << 2;
                *(uint2*)&Ah[m * 40 + kc] = H;
                *(uint2*)&Al[m * 40 + kc] = L;
            } else {
                int k = f >> 5, mc = (f & 31) << 2;
                *(uint2*)&Ah[k * 136 + mc] = H;
                *(uint2*)&Al[k * 136 + mc] = L;
            }
        }
    };
    auto storeB = [&](int buf) {
        __nv_bfloat16* Bh = (__nv_bfloat16*)(smraw + 4 * A_SEG + (buf * 2 + 0) * B_SEG);
        __nv_bfloat16* Bl = (__nv_bfloat16*)(smraw + 4 * A_SEG + (buf * 2 + 1) * B_SEG);
        #pragma unroll
        for (int i = 0; i < 2; i++) {
            int f = tid + i * 256;
            __nv_bfloat16 h[4], l[4];
            #pragma unroll
            for (int j = 0; j < 4; j++) split_bf16(rb[i * 4 + j], h[j], l[j]);
            uint2 H = make_uint2(pk(h[0], h[1]), pk(h[2], h[3]));
            uint2 L = make_uint2(pk(l[0], l[1]), pk(l[2], l[3]));
            if (B_T == 0) {
                int k = f >> 4, nc = (f & 15) << 2;
                *(uint2*)&Bh[k * 72 + nc] = H;
                *(uint2*)&Bl[k * 72 + nc] = L;
            } else {
                int n = f >> 3, kc = (f & 7) << 2;
                *(uint2*)&Bh[n * 40 + kc] = H;
                *(uint2*)&Bl[n * 40 + kc] = L;
            }
        }
    };

    float acc[2][4][4];
    #pragma unroll
    for (int tm = 0; tm < 2; tm++)
        #pragma unroll
        for (int tn = 0; tn < 4; tn++)
            #pragma unroll
            for (int r = 0; r < 4; r++) acc[tm][tn][r] = 0.f;

    const int nk = K >> 5;

    loadA(0); loadB(0);
    storeA(0); storeB(0);
    __syncthreads();

    for (int kt = 0; kt < nk; kt++) {
        const int cur = kt & 1;
        if (kt + 1 < nk) { loadA((kt + 1) << 5); loadB((kt + 1) << 5); }

        const uint32_t AhB = smBase + (cur * 2 + 0) * A_SEG;
        const uint32_t AlB = smBase + (cur * 2 + 1) * A_SEG;
        const uint32_t BhB = smBase + 4 * A_SEG + (cur * 2 + 0) * B_SEG;
        const uint32_t BlB = smBase + 4 * A_SEG + (cur * 2 + 1) * B_SEG;

        #pragma unroll
        for (int ks = 0; ks < 2; ks++) {
            uint32_t ah[2][4], al[2][4], bh[4][2], bl[4][2];
            #pragma unroll
            for (int tm = 0; tm < 2; tm++) {
                if (A_T == 0) {
                    ldsm4(ah[tm][0], ah[tm][1], ah[tm][2], ah[tm][3], AhB + aOff[tm] + ks * aStep);
                    ldsm4(al[tm][0], al[tm][1], al[tm][2], al[tm][3], AlB + aOff[tm] + ks * aStep);
                } else {
                    ldsm4t(ah[tm][0], ah[tm][1], ah[tm][2], ah[tm][3], AhB + aOff[tm] + ks * aStep);
                    ldsm4t(al[tm][0], al[tm][1], al[tm][2], al[tm][3], AlB + aOff[tm] + ks * aStep);
                }
            }
            #pragma unroll
            for (int p = 0; p < 2; p++) {
                uint32_t r0, r1, r2, r3;
                if (B_T == 0) ldsm4t(r0, r1, r2, r3, BhB + bOff[p] + ks * bStep);
                else          ldsm4 (r0, r1, r2, r3, BhB + bOff[p] + ks * bStep);
                bh[p * 2 + 0][0] = r0; bh[p * 2 + 0][1] = r1;
                bh[p * 2 + 1][0] = r2; bh[p * 2 + 1][1] = r3;
                if (B_T == 0) ldsm4t(r0, r1, r2, r3, BlB + bOff[p] + ks * bStep);
                else          ldsm4 (r0, r1, r2, r3, BlB + bOff[p] + ks * bStep);
                bl[p * 2 + 0][0] = r0; bl[p * 2 + 0][1] = r1;
                bl[p * 2 + 1][0] = r2; bl[p * 2 + 1][1] = r3;
            }
            #pragma unroll
            for (int tm = 0; tm < 2; tm++)
                #pragma unroll
                for (int tn = 0; tn < 4; tn++) {
                    mma_bf16(acc[tm][tn], ah[tm], bh[tn]);
                    mma_bf16(acc[tm][tn], ah[tm], bl[tn]);
                    mma_bf16(acc[tm][tn], al[tm], bh[tn]);
                }
        }

        if (kt + 1 < nk) { storeA(cur ^ 1); storeB(cur ^ 1); }
        __syncthreads();
    }

    // ---- epilogue: exp + row-sum path (scores) ----
    if (EXPZ == 1) {
        #pragma unroll
        for (int tm = 0; tm < 2; tm++) {
            #pragma unroll
            for (int half = 0; half < 2; half++) {
                const int row = bm + m0 + tm * 16 + g + half * 8;
                float rs = 0.f;
                #pragma unroll
                for (int tn = 0; tn < 4; tn++) {
                    const int col = bn + n0 + tn * 8 + 2 * tg;
                    float2 v;
                    v.x = __expf(acc[tm][tn][half * 2 + 0] * scale);
                    v.y = __expf(acc[tm][tn][half * 2 + 1] * scale);
                    rs += v.x + v.y;
                    *(float2*)(C + (size_t)row * ldc + col) = v;
                }
                rs += __shfl_xor_sync(0xffffffffu, rs, 1);
                rs += __shfl_xor_sync(0xffffffffu, rs, 2);
                if (tg == 0) atomicAdd(Zp + row, rs);
            }
        }
        return;
    }

    // ---- normal epilogue ----
    #pragma unroll
    for (int tm = 0; tm < 2; tm++) {
        #pragma unroll
        for (int tn = 0; tn < 4; tn++) {
            const int col = bn + n0 + tn * 8 + 2 * tg;
            float2 bb = make_float2(0.f, 0.f);
            if (HAS_BIAS) bb = *(const float2*)(biasp + col);
            #pragma unroll
            for (int half = 0; half < 2; half++) {
                const int row = bm + m0 + tm * 16 + g + half * 8;
                float2 v;
                v.x = acc[tm][tn][half * 2 + 0];
                v.y = acc[tm][tn][half * 2 + 1];
                if (HAS_SCALE) { v.x *= scale; v.y *= scale; }
                if (HAS_BIAS)  { v.x += bb.x;  v.y += bb.y;  }
                if (RELU)      { v.x = fmaxf(v.x, 0.f); v.y = fmaxf(v.y, 0.f); }
                *(float2*)(C + (size_t)row * ldc + col) = v;
            }
        }
    }
}

// zero the Z accumulator each launch
__global__ void zerok(float* __restrict__ p, int n)
{
    int i = blockIdx.x * blockDim.x + threadIdx.x;
    if (i < n) p[i] = 0.f;
}

// =====================================================================
extern "C" void kernel_launch(void* const* d_in, const int* in_sizes, int n_in,
                              void* d_out, int out_size)
{
    const float* x  = (const float*)d_in[0];
    const float* Wq = (const float*)d_in[1];
    const float* bq = (const float*)d_in[2];
    const float* Wk = (const float*)d_in[3];
    const float* bk = (const float*)d_in[4];
    const float* Wv = (const float*)d_in[5];
    const float* bv = (const float*)d_in[6];
    const float* Wp = (const float*)d_in[7];
    const float* bp = (const float*)d_in[8];
    const float* W1 = (const float*)d_in[9];
    const float* b1 = (const float*)d_in[10];
    const float* W2 = (const float*)d_in[11];
    const float* b2 = (const float*)d_in[12];
    float* out = (float*)d_out;

    float *Q, *K, *V, *attn, *Z, *concat, *proj, *hidden;
    cudaGetSymbolAddress((void**)&Q,      g_Q);
    cudaGetSymbolAddress((void**)&K,      g_K);
    cudaGetSymbolAddress((void**)&V,      g_V);
    cudaGetSymbolAddress((void**)&attn,   g_attn);
    cudaGetSymbolAddress((void**)&Z,      g_Z);
    cudaGetSymbolAddress((void**)&concat, g_concat);
    cudaGetSymbolAddress((void**)&proj,   g_proj);
    cudaGetSymbolAddress((void**)&hidden, g_hidden);

    cudaFuncSetAttribute(mmbf<0,0,1,0,0,0>, cudaFuncAttributeMaxDynamicSharedMemorySize, MMBF_SMEM);
    cudaFuncSetAttribute(mmbf<0,1,0,0,1,1>, cudaFuncAttributeMaxDynamicSharedMemorySize, MMBF_SMEM);
    cudaFuncSetAttribute(mmbf<1,0,0,0,0,2>, cudaFuncAttributeMaxDynamicSharedMemorySize, MMBF_SMEM);
    cudaFuncSetAttribute(mmbf<0,0,1,1,0,0>, cudaFuncAttributeMaxDynamicSharedMemorySize, MMBF_SMEM);

    // 0) zero Z
    zerok<<<(NH * SEQ + 255) / 256, 256>>>(Z, NH * SEQ);

    // 1) QKV: per-head NN gemm, z = head
    {
        dim3 grid(1, SEQ / 128, NH);
        mmbf<0,0,1,0,0,0><<<grid, 256, MMBF_SMEM>>>(x, Wq, bq, Q, nullptr, DM, DM, HDIM, HDIM,
                                                    0, (size_t)DM * HDIM, (size_t)SEQ * HDIM, HDIM, 1.f);
        mmbf<0,0,1,0,0,0><<<grid, 256, MMBF_SMEM>>>(x, Wk, bk, K, nullptr, DM, DM, HDIM, HDIM,
                                                    0, (size_t)DM * HDIM, (size_t)SEQ * HDIM, HDIM, 1.f);
        mmbf<0,0,1,0,0,0><<<grid, 256, MMBF_SMEM>>>(x, Wv, bv, V, nullptr, DM, DM, HDIM, HDIM,
                                                    0, (size_t)DM * HDIM, (size_t)SEQ * HDIM, HDIM, 1.f);
    }

    // 2) attn[h,s,t] = exp(Q.K/8), Z[h,s] += row sums (fused softmax part 1)
    {
        dim3 grid(SEQ / 64, SEQ / 128, NH);
        mmbf<0,1,0,0,1,1><<<grid, 256, MMBF_SMEM>>>(Q, K, nullptr, attn, Z, HDIM, HDIM, HDIM, SEQ,
                                                    (size_t)SEQ * HDIM, (size_t)SEQ * HDIM,
                                                    (size_t)SEQ * SEQ, 0, 0.125f);
    }

    // 3) concat[t, h*64+e] = sum_s (attn[h,s,t]/Z[h,s]) V[h,s,e]  (softmax part 2 fused into A staging)
    {
        dim3 grid(1, SEQ / 128, NH);
        mmbf<1,0,0,0,0,2><<<grid, 256, MMBF_SMEM>>>(attn, V, nullptr, concat, Z, SEQ, SEQ, HDIM, DM,
                                                    (size_t)SEQ * SEQ, (size_t)SEQ * HDIM,
                                                    (size_t)HDIM, 0, 1.f);
    }

    // 4) proj = concat @ Wp + bp
    mmbf<0,0,1,0,0,0><<<dim3(DM / 64, SEQ / 128, 1), 256, MMBF_SMEM>>>(
        concat, Wp, bp, proj, nullptr, DM, DM, DM, DM, 0, 0, 0, 0, 1.f);

    // 5) hidden = relu(proj @ W1 + b1)
    mmbf<0,0,1,1,0,0><<<dim3(FFD / 64, SEQ / 128, 1), 256, MMBF_SMEM>>>(
        proj, W1, b1, hidden, nullptr, DM, DM, FFD, FFD, 0, 0, 0, 0, 1.f);

    // 6) out = hidden @ W2 + b2
    mmbf<0,0,1,0,0,0><<<dim3(DM / 64, SEQ / 128, 1), 256, MMBF_SMEM>>>(
        hidden, W2, b2, out, nullptr, FFD, FFD, DM, DM, 0, 0, 0, 0, 1.f);
}

// round 6
// speedup vs baseline: 2.7267x; 1.0150x over previous
#include <cuda_runtime.h>
#include <cuda_fp16.h>
#include <cstdint>

#define SEQ  2048
#define DM   1024
#define NH   16
#define HDIM 64
#define FFD  4096
#define NQKV 3072

// ---------------- scratch (no allocations allowed) ----------------
__device__ __half g_Xsp[2u * SEQ * DM];
__device__ __half g_Wqkvt[2u * NQKV * DM];
__device__ __half g_Wpt[2u * DM * DM];
__device__ __half g_W1t[2u * FFD * DM];
__device__ __half g_W2t[2u * DM * FFD];
__device__ __half g_Qsp[NH * 2 * SEQ * HDIM];
__device__ __half g_Ksp[NH * 2 * SEQ * HDIM];
__device__ float  g_Vf[NH * SEQ * HDIM];
__device__ __half g_Vn[NH * 2 * HDIM * SEQ];
__device__ __half g_P[(size_t)NH * SEQ * SEQ];
__device__ float  g_Z[NH * SEQ];
__device__ float  g_Zinv[NH * SEQ];
__device__ float  g_concatf[SEQ * DM];
__device__ __half g_Csp[2u * SEQ * DM];
__device__ __half g_Projsp[2u * SEQ * DM];
__device__ __half g_Hsp[2u * SEQ * FFD];

// ---------------- helpers ----------------
__device__ __forceinline__ void split_h(float a, __half& h, __half& l) {
    h = __float2half_rn(a);
    l = __float2half_rn(a - __half2float(h));
}
__device__ __forceinline__ uint32_t pkh(__half a, __half b) {
    __half2 t(a, b);
    return *reinterpret_cast<uint32_t*>(&t);
}
__device__ __forceinline__ void ldsm4(uint32_t& r0, uint32_t& r1, uint32_t& r2, uint32_t& r3, uint32_t a) {
    asm volatile("ldmatrix.sync.aligned.m8n8.x4.shared.b16 {%0,%1,%2,%3}, [%4];"
                 : "=r"(r0), "=r"(r1), "=r"(r2), "=r"(r3) : "r"(a));
}
__device__ __forceinline__ void mma_h(float c[4], const uint32_t a[4], const uint32_t b[2]) {
    asm volatile(
        "mma.sync.aligned.m16n8k16.row.col.f32.f16.f16.f32 "
        "{%0,%1,%2,%3}, {%4,%5,%6,%7}, {%8,%9}, {%0,%1,%2,%3};"
        : "+f"(c[0]), "+f"(c[1]), "+f"(c[2]), "+f"(c[3])
        : "r"(a[0]), "r"(a[1]), "r"(a[2]), "r"(a[3]), "r"(b[0]), "r"(b[1]));
}
__device__ __forceinline__ void cp16(uint32_t dst, const void* src) {
    asm volatile("cp.async.cg.shared.global [%0], [%1], 16;" :: "r"(dst), "l"(src));
}
__device__ __forceinline__ void cp_commit() {
    asm volatile("cp.async.commit_group;" ::: "memory");
}
template <int N>
__device__ __forceinline__ void cp_wait() {
    asm volatile("cp.async.wait_group %0;" :: "n"(N) : "memory");
}

// =====================================================================
// fp16 split-2 mma.sync GEMM.  CTA 128(M)x64(N), BK=32, 128 threads,
// 4 warps 2m x 2n, warp tile 64x32.  Operands pre-split fp16 planes,
// k-contiguous: A[p][M][lda], B[p][N][ldb].  cp.async 2-stage.
// smem pitch 40 halves (80B) -> conflict-free LDSM.
// EPI: 0 fp32+bias(+relu), 1 fp16 hi/lo planes+bias(+relu),
//      2 exp(scale*acc)->P fp16 + column-sum atomics into Z,
//      3 atomicAdd fp32 (split-K AV), 4 QKV triple-output.
// ANP: # A planes (2 = split, 1 = single).  SKBITS: split-K bits in z.
// =====================================================================
#define BM 128
#define BN 64
#define PITCH 80   // bytes per smem row
#define ASEG 10240 // 128*80
#define BSEG 5120  // 64*80

template <int EPI, int ANP, int RELU, int SKBITS>
__global__ void __launch_bounds__(128, 3)
gg(const __half* __restrict__ A, const __half* __restrict__ B,
   const float* __restrict__ bias, const float* __restrict__ bias2,
   const float* __restrict__ bias3, void* __restrict__ Cv,
   float* __restrict__ Zb,
   int K, int lda, int ldb, int ldc,
   size_t aZ, size_t bZ, size_t cZ, size_t pA, size_t pB, size_t pC,
   float scale)
{
    extern __shared__ __align__(16) unsigned char sm[];
    const uint32_t smb = (uint32_t)__cvta_generic_to_shared(sm);
    const int STG = ANP * ASEG + 2 * BSEG;

    const int tid = threadIdx.x;
    const int warp = tid >> 5, lane = tid & 31;
    const int g = lane >> 2, tg = lane & 3;
    const int b3 = (lane >> 3) & 1, b4 = (lane >> 4) & 1;
    const int m0 = (warp & 1) * 64, n0 = (warp >> 1) * 32;

    const int z = blockIdx.z;
    const int zhead = z >> SKBITS;
    const int ksplit = z & ((1 << SKBITS) - 1);
    const int bm = blockIdx.y * BM;
    const int bn = blockIdx.x * BN;

    const __half* Ag = A + zhead * aZ + (size_t)ksplit * K;
    const __half* Bg = B + zhead * bZ + (size_t)ksplit * K;

    // ldsm offsets (bytes within a plane segment)
    uint32_t aOff[4], bOff[2];
    #pragma unroll
    for (int tm = 0; tm < 4; tm++)
        aOff[tm] = ((m0 + tm * 16 + (lane & 7) + b3 * 8) * 40 + b4 * 8) * 2;
    #pragma unroll
    for (int q = 0; q < 2; q++)
        bOff[q] = ((n0 + q * 16 + (lane & 7) + b4 * 8) * 40 + b3 * 8) * 2;

    auto ldgsts = [&](int st, int slab) {
        const int k0 = slab << 5;
        #pragma unroll
        for (int p = 0; p < ANP; p++)
            #pragma unroll
            for (int i = 0; i < 4; i++) {
                int idx = tid + i * 128;
                int row = idx >> 2, kc = idx & 3;
                cp16(smb + st * STG + p * ASEG + row * PITCH + kc * 16,
                     Ag + p * pA + (size_t)(bm + row) * lda + k0 + kc * 8);
            }
        #pragma unroll
        for (int p = 0; p < 2; p++)
            #pragma unroll
            for (int i = 0; i < 2; i++) {
                int idx = tid + i * 128;
                int row = idx >> 2, kc = idx & 3;
                cp16(smb + st * STG + ANP * ASEG + p * BSEG + row * PITCH + kc * 16,
                     Bg + p * pB + (size_t)(bn + row) * ldb + k0 + kc * 8);
            }
        cp_commit();
    };

    float acc[4][4][4];
    #pragma unroll
    for (int tm = 0; tm < 4; tm++)
        #pragma unroll
        for (int tn = 0; tn < 4; tn++)
            #pragma unroll
            for (int r = 0; r < 4; r++) acc[tm][tn][r] = 0.f;

    const int ns = K >> 5;
    ldgsts(0, 0);
    ldgsts(1, 1);
    cp_wait<1>();
    __syncthreads();

    for (int i = 0; i < ns; i++) {
        const int buf = i & 1;
        const uint32_t aB = smb + buf * STG;
        const uint32_t bB = smb + buf * STG + ANP * ASEG;
        #pragma unroll
        for (int ks = 0; ks < 2; ks++) {
            uint32_t af[4][2][4], bf[2][4][2];
            #pragma unroll
            for (int tm = 0; tm < 4; tm++)
                #pragma unroll
                for (int p = 0; p < ANP; p++)
                    ldsm4(af[tm][p][0], af[tm][p][1], af[tm][p][2], af[tm][p][3],
                          aB + p * ASEG + aOff[tm] + ks * 32);
            #pragma unroll
            for (int p = 0; p < 2; p++)
                #pragma unroll
                for (int q = 0; q < 2; q++) {
                    uint32_t r0, r1, r2, r3;
                    ldsm4(r0, r1, r2, r3, bB + p * BSEG + bOff[q] + ks * 32);
                    bf[p][q * 2 + 0][0] = r0; bf[p][q * 2 + 0][1] = r1;
                    bf[p][q * 2 + 1][0] = r2; bf[p][q * 2 + 1][1] = r3;
                }
            #pragma unroll
            for (int tm = 0; tm < 4; tm++)
                #pragma unroll
                for (int tn = 0; tn < 4; tn++) {
                    mma_h(acc[tm][tn], af[tm][0], bf[0][tn]);
                    mma_h(acc[tm][tn], af[tm][0], bf[1][tn]);
                    if (ANP == 2) mma_h(acc[tm][tn], af[tm][1], bf[0][tn]);
                }
        }
        __syncthreads();
        if (i + 2 < ns) ldgsts(buf, i + 2);
        if (i + 1 < ns) {
            if (i + 2 < ns) cp_wait<1>(); else cp_wait<0>();
            __syncthreads();
        }
    }

    // ------------------ epilogues ------------------
    if (EPI == 2) {
        // P = exp(scale*acc) fp16; Z[col] += column sums
        __half* Pz = (__half*)Cv + zhead * cZ;
        float cs[4][2];
        #pragma unroll
        for (int tn = 0; tn < 4; tn++) { cs[tn][0] = 0.f; cs[tn][1] = 0.f; }
        #pragma unroll
        for (int tm = 0; tm < 4; tm++)
            #pragma unroll
            for (int half = 0; half < 2; half++) {
                const int row = bm + m0 + tm * 16 + g + half * 8;
                #pragma unroll
                for (int tn = 0; tn < 4; tn++) {
                    float px = __expf(acc[tm][tn][half * 2 + 0] * scale);
                    float py = __expf(acc[tm][tn][half * 2 + 1] * scale);
                    cs[tn][0] += px; cs[tn][1] += py;
                    *(uint32_t*)(Pz + (size_t)row * ldc + bn + n0 + tn * 8 + 2 * tg) =
                        pkh(__float2half_rn(px), __float2half_rn(py));
                }
            }
        float* Zp = Zb + (size_t)zhead * SEQ;
        #pragma unroll
        for (int tn = 0; tn < 4; tn++)
            #pragma unroll
            for (int j = 0; j < 2; j++) {
                float v = cs[tn][j];
                v += __shfl_xor_sync(0xffffffffu, v, 4);
                v += __shfl_xor_sync(0xffffffffu, v, 8);
                v += __shfl_xor_sync(0xffffffffu, v, 16);
                if (lane < 4) atomicAdd(Zp + bn + n0 + tn * 8 + 2 * tg + j, v);
            }
    } else if (EPI == 3) {
        float* C = (float*)Cv;
        #pragma unroll
        for (int tm = 0; tm < 4; tm++)
            #pragma unroll
            for (int half = 0; half < 2; half++) {
                const int row = bm + m0 + tm * 16 + g + half * 8;
                #pragma unroll
                for (int tn = 0; tn < 4; tn++) {
                    const int nc = n0 + tn * 8 + 2 * tg;
                    float* dst = C + (size_t)row * DM + zhead * 64 + nc;
                    atomicAdd(dst,     acc[tm][tn][half * 2 + 0]);
                    atomicAdd(dst + 1, acc[tm][tn][half * 2 + 1]);
                }
            }
    } else if (EPI == 4) {
        const int seg = bn >> 10;
        const int hh  = (bn >> 6) & 15;
        const float* bsel = (seg == 0) ? bias : (seg == 1) ? bias2 : bias3;
        #pragma unroll
        for (int tn = 0; tn < 4; tn++) {
            const int e = n0 + tn * 8 + 2 * tg;
            float2 bb = *(const float2*)(bsel + hh * 64 + e);
            #pragma unroll
            for (int tm = 0; tm < 4; tm++)
                #pragma unroll
                for (int half = 0; half < 2; half++) {
                    const int row = bm + m0 + tm * 16 + g + half * 8;
                    float vx = acc[tm][tn][half * 2 + 0] + bb.x;
                    float vy = acc[tm][tn][half * 2 + 1] + bb.y;
                    if (seg == 2) {
                        *(float2*)(g_Vf + ((size_t)hh * SEQ + row) * HDIM + e) =
                            make_float2(vx, vy);
                    } else {
                        __half hx, lx, hy, ly;
                        split_h(vx, hx, lx); split_h(vy, hy, ly);
                        __half* O = (seg == 0) ? g_Qsp : g_Ksp;
                        size_t base = (size_t)hh * 2 * SEQ * HDIM + (size_t)row * HDIM + e;
                        *(uint32_t*)(O + base)                        = pkh(hx, hy);
                        *(uint32_t*)(O + base + (size_t)SEQ * HDIM)   = pkh(lx, ly);
                    }
                }
        }
    } else if (EPI == 1) {
        __half* Ch = (__half*)Cv + zhead * cZ;
        __half* Cl = Ch + pC;
        #pragma unroll
        for (int tn = 0; tn < 4; tn++) {
            const int col = bn + n0 + tn * 8 + 2 * tg;
            float2 bb = *(const float2*)(bias + col);
            #pragma unroll
            for (int tm = 0; tm < 4; tm++)
                #pragma unroll
                for (int half = 0; half < 2; half++) {
                    const int row = bm + m0 + tm * 16 + g + half * 8;
                    float vx = acc[tm][tn][half * 2 + 0] + bb.x;
                    float vy = acc[tm][tn][half * 2 + 1] + bb.y;
                    if (RELU) { vx = fmaxf(vx, 0.f); vy = fmaxf(vy, 0.f); }
                    __half hx, lx, hy, ly;
                    split_h(vx, hx, lx); split_h(vy, hy, ly);
                    size_t o = (size_t)row * ldc + col;
                    *(uint32_t*)(Ch + o) = pkh(hx, hy);
                    *(uint32_t*)(Cl + o) = pkh(lx, ly);
                }
        }
    } else {
        float* C = (float*)Cv + zhead * cZ;
        #pragma unroll
        for (int tn = 0; tn < 4; tn++) {
            const int col = bn + n0 + tn * 8 + 2 * tg;
            float2 bb = *(const float2*)(bias + col);
            #pragma unroll
            for (int tm = 0; tm < 4; tm++)
                #pragma unroll
                for (int half = 0; half < 2; half++) {
                    const int row = bm + m0 + tm * 16 + g + half * 8;
                    float vx = acc[tm][tn][half * 2 + 0] + bb.x;
                    float vy = acc[tm][tn][half * 2 + 1] + bb.y;
                    if (RELU) { vx = fmaxf(vx, 0.f); vy = fmaxf(vy, 0.f); }
                    *(float2*)(C + (size_t)row * ldc + col) = make_float2(vx, vy);
                }
        }
    }
}

// =====================================================================
// prep kernels
// =====================================================================
__global__ void splitf(const float* __restrict__ in, __half* __restrict__ out, size_t n)
{
    size_t i = (size_t)blockIdx.x * blockDim.x + threadIdx.x;
    if (i < n) {
        __half h, l;
        split_h(in[i], h, l);
        out[i] = h; out[n + i] = l;
    }
}

// W fp32 [z][K][N] -> O fp16 planes [p][rows][K], row = rowOff + z*zstep + n
__global__ void tspw(const float* __restrict__ W, __half* __restrict__ O,
                     int K, int N, size_t plane, int rowOff, int zstep)
{
    __shared__ float t[32][33];
    const int z = blockIdx.z;
    const int n0 = blockIdx.x * 32, k0 = blockIdx.y * 32;
    const int tx = threadIdx.x, ty = threadIdx.y;
    const float* Wb = W + (size_t)z * K * N;
    #pragma unroll
    for (int i = 0; i < 32; i += 8)
        t[ty + i][tx] = Wb[(size_t)(k0 + ty + i) * N + n0 + tx];
    __syncthreads();
    #pragma unroll
    for (int i = 0; i < 32; i += 8) {
        __half h, l;
        split_h(t[tx][ty + i], h, l);
        size_t o = (size_t)(rowOff + z * zstep + n0 + ty + i) * K + k0 + tx;
        O[o] = h; O[plane + o] = l;
    }
}

// Vn[h][p][e][s] = split(Vf[h][s][e] * Zinv[h][s])
__global__ void rescaleV(const float* __restrict__ Vf, const float* __restrict__ Zi,
                         __half* __restrict__ Vn)
{
    __shared__ float t[32][33];
    const int h = blockIdx.z;
    const int e0 = blockIdx.x * 32, s0 = blockIdx.y * 32;
    const int tx = threadIdx.x, ty = threadIdx.y;
    const float* Vb = Vf + (size_t)h * SEQ * HDIM;
    const float* Zp = Zi + (size_t)h * SEQ;
    #pragma unroll
    for (int i = 0; i < 32; i += 8) {
        int s = s0 + ty + i;
        t[ty + i][tx] = Vb[(size_t)s * HDIM + e0 + tx] * Zp[s];
    }
    __syncthreads();
    __half* Ob = Vn + (size_t)h * 2 * HDIM * SEQ;
    #pragma unroll
    for (int i = 0; i < 32; i += 8) {
        __half hv, lv;
        split_h(t[tx][ty + i], hv, lv);
        size_t o = (size_t)(e0 + ty + i) * SEQ + s0 + tx;
        Ob[o] = hv; Ob[(size_t)HDIM * SEQ + o] = lv;
    }
}

__global__ void zerok(float* __restrict__ p, int n)
{
    int i = blockIdx.x * blockDim.x + threadIdx.x;
    if (i < n) p[i] = 0.f;
}
__global__ void recipk(const float* __restrict__ a, float* __restrict__ b, int n)
{
    int i = blockIdx.x * blockDim.x + threadIdx.x;
    if (i < n) b[i] = 1.f / a[i];
}

// =====================================================================
extern "C" void kernel_launch(void* const* d_in, const int* in_sizes, int n_in,
                              void* d_out, int out_size)
{
    const float* x  = (const float*)d_in[0];
    const float* Wq = (const float*)d_in[1];
    const float* bq = (const float*)d_in[2];
    const float* Wk = (const float*)d_in[3];
    const float* bk = (const float*)d_in[4];
    const float* Wv = (const float*)d_in[5];
    const float* bv = (const float*)d_in[6];
    const float* Wp = (const float*)d_in[7];
    const float* bp = (const float*)d_in[8];
    const float* W1 = (const float*)d_in[9];
    const float* b1 = (const float*)d_in[10];
    const float* W2 = (const float*)d_in[11];
    const float* b2 = (const float*)d_in[12];
    float* out = (float*)d_out;

    __half *Xsp, *Wqkvt, *Wpt, *W1t, *W2t, *Qsp, *Ksp, *Vn, *P, *Csp, *Projsp, *Hsp;
    float *Vf, *Z, *Zinv, *concatf;
    cudaGetSymbolAddress((void**)&Xsp,    g_Xsp);
    cudaGetSymbolAddress((void**)&Wqkvt,  g_Wqkvt);
    cudaGetSymbolAddress((void**)&Wpt,    g_Wpt);
    cudaGetSymbolAddress((void**)&W1t,    g_W1t);
    cudaGetSymbolAddress((void**)&W2t,    g_W2t);
    cudaGetSymbolAddress((void**)&Qsp,    g_Qsp);
    cudaGetSymbolAddress((void**)&Ksp,    g_Ksp);
    cudaGetSymbolAddress((void**)&Vf,     g_Vf);
    cudaGetSymbolAddress((void**)&Vn,     g_Vn);
    cudaGetSymbolAddress((void**)&P,      g_P);
    cudaGetSymbolAddress((void**)&Z,      g_Z);
    cudaGetSymbolAddress((void**)&Zinv,   g_Zinv);
    cudaGetSymbolAddress((void**)&concatf, g_concatf);
    cudaGetSymbolAddress((void**)&Csp,    g_Csp);
    cudaGetSymbolAddress((void**)&Projsp, g_Projsp);
    cudaGetSymbolAddress((void**)&Hsp,    g_Hsp);

    const int SM2 = 2 * (2 * ASEG + 2 * BSEG);  // 61440
    const int SM1 = 2 * (1 * ASEG + 2 * BSEG);  // 40960
    cudaFuncSetAttribute(gg<4,2,0,0>, cudaFuncAttributeMaxDynamicSharedMemorySize, SM2);
    cudaFuncSetAttribute(gg<2,2,0,0>, cudaFuncAttributeMaxDynamicSharedMemorySize, SM2);
    cudaFuncSetAttribute(gg<3,1,0,2>, cudaFuncAttributeMaxDynamicSharedMemorySize, SM1);
    cudaFuncSetAttribute(gg<1,2,0,0>, cudaFuncAttributeMaxDynamicSharedMemorySize, SM2);
    cudaFuncSetAttribute(gg<1,2,1,0>, cudaFuncAttributeMaxDynamicSharedMemorySize, SM2);
    cudaFuncSetAttribute(gg<0,2,0,0>, cudaFuncAttributeMaxDynamicSharedMemorySize, SM2);

    dim3 tb(32, 8);
    // prep: split x, transpose+split weights, zero accumulators
    splitf<<<(SEQ * DM + 255) / 256, 256>>>(x, Xsp, (size_t)SEQ * DM);
    tspw<<<dim3(2, 32, NH), tb>>>(Wq, Wqkvt, DM, HDIM, (size_t)NQKV * DM, 0,    64);
    tspw<<<dim3(2, 32, NH), tb>>>(Wk, Wqkvt, DM, HDIM, (size_t)NQKV * DM, 1024, 64);
    tspw<<<dim3(2, 32, NH), tb>>>(Wv, Wqkvt, DM, HDIM, (size_t)NQKV * DM, 2048, 64);
    tspw<<<dim3(32, 32, 1),  tb>>>(Wp, Wpt, DM, DM,  (size_t)DM * DM,  0, 0);
    tspw<<<dim3(128, 32, 1), tb>>>(W1, W1t, DM, FFD, (size_t)FFD * DM, 0, 0);
    tspw<<<dim3(32, 128, 1), tb>>>(W2, W2t, FFD, DM, (size_t)DM * FFD, 0, 0);
    zerok<<<(NH * SEQ + 255) / 256, 256>>>(Z, NH * SEQ);
    zerok<<<(SEQ * DM + 255) / 256, 256>>>(concatf, SEQ * DM);

    // 1) fused QKV: [2048 x 3072] = Xsp @ Wqkvt^T ; epilogue scatters Q/K/V
    gg<4,2,0,0><<<dim3(NQKV / BN, SEQ / BM, 1), 128, SM2>>>(
        Xsp, Wqkvt, bq, bk, bv, nullptr, nullptr,
        DM, DM, DM, 0, 0, 0, 0, (size_t)SEQ * DM, (size_t)NQKV * DM, 0, 1.f);

    // 2) P[h][t][s] = exp(K[t].Q[s]/8) fp16; Z[h][s] += column sums
    gg<2,2,0,0><<<dim3(SEQ / BN, SEQ / BM, NH), 128, SM2>>>(
        Ksp, Qsp, nullptr, nullptr, nullptr, P, Z,
        HDIM, HDIM, HDIM, SEQ,
        (size_t)2 * SEQ * HDIM, (size_t)2 * SEQ * HDIM, (size_t)SEQ * SEQ,
        (size_t)SEQ * HDIM, (size_t)SEQ * HDIM, 0, 0.125f);

    // 3) Zinv; Vn[h][p][e][s] = split(V/Z)
    recipk<<<(NH * SEQ + 255) / 256, 256>>>(Z, Zinv, NH * SEQ);
    rescaleV<<<dim3(2, 64, NH), tb>>>(Vf, Zinv, Vn);

    // 4) AV split-K=4: concatf[t][h*64+e] += P[t][s-chunk] . Vn[e][s-chunk]
    gg<3,1,0,2><<<dim3(1, SEQ / BM, NH * 4), 128, SM1>>>(
        P, Vn, nullptr, nullptr, nullptr, concatf, nullptr,
        SEQ / 4, SEQ, SEQ, DM,
        (size_t)SEQ * SEQ, (size_t)2 * HDIM * SEQ, 0,
        0, (size_t)HDIM * SEQ, 0, 1.f);

    // 5) split concat -> fp16 planes
    splitf<<<(SEQ * DM + 255) / 256, 256>>>(concatf, Csp, (size_t)SEQ * DM);

    // 6) proj = concat @ Wp + bp  (fp16 planes out)
    gg<1,2,0,0><<<dim3(DM / BN, SEQ / BM, 1), 128, SM2>>>(
        Csp, Wpt, bp, nullptr, nullptr, Projsp, nullptr,
        DM, DM, DM, DM, 0, 0, 0,
        (size_t)SEQ * DM, (size_t)DM * DM, (size_t)SEQ * DM, 1.f);

    // 7) hidden = relu(proj @ W1 + b1)  (fp16 planes out)
    gg<1,2,1,0><<<dim3(FFD / BN, SEQ / BM, 1), 128, SM2>>>(
        Projsp, W1t, b1, nullptr, nullptr, Hsp, nullptr,
        DM, DM, DM, FFD, 0, 0, 0,
        (size_t)SEQ * DM, (size_t)FFD * DM, (size_t)SEQ * FFD, 1.f);

    // 8) out = hidden @ W2 + b2  (fp32)
    gg<0,2,0,0><<<dim3(DM / BN, SEQ / BM, 1), 128, SM2>>>(
        Hsp, W2t, b2, nullptr, nullptr, out, nullptr,
        FFD, FFD, FFD, DM, 0, 0, 0,
        (size_t)SEQ * FFD, (size_t)DM * FFD, 0, 1.f);
}

// round 7
// speedup vs baseline: 3.0708x; 1.1262x over previous
#include <cuda_runtime.h>
#include <cuda_fp16.h>
#include <cstdint>

#define SEQ  2048
#define DM   1024
#define NH   16
#define HDIM 64
#define FFD  4096
#define NQKV 3072

// ---------------- scratch (no allocations allowed) ----------------
__device__ __half g_Xsp[2u * SEQ * DM];
__device__ __half g_Wqkvt[2u * NQKV * DM];
__device__ __half g_Wpt[2u * DM * DM];
__device__ __half g_W1t[2u * FFD * DM];
__device__ __half g_W2t[2u * DM * FFD];
__device__ __half g_Qsp[NH * 2 * SEQ * HDIM];
__device__ __half g_Ksp[NH * 2 * SEQ * HDIM];
__device__ float  g_Vf[NH * SEQ * HDIM];
__device__ __half g_Vn[NH * 2 * HDIM * SEQ];
__device__ __half g_P[(size_t)NH * SEQ * SEQ];
__device__ float  g_Z[NH * SEQ];
__device__ float  g_Zinv[NH * SEQ];
__device__ float  g_cpart[2u * SEQ * DM];      // split-K partials
__device__ __half g_Csp[2u * SEQ * DM];
__device__ __half g_Projsp[2u * SEQ * DM];
__device__ __half g_Hsp[(size_t)SEQ * FFD];    // hi plane only

// ---------------- helpers ----------------
__device__ __forceinline__ void split_h(float a, __half& h, __half& l) {
    h = __float2half_rn(a);
    l = __float2half_rn(a - __half2float(h));
}
__device__ __forceinline__ uint32_t pkh(__half a, __half b) {
    __half2 t(a, b);
    return *reinterpret_cast<uint32_t*>(&t);
}
__device__ __forceinline__ void ldsm4(uint32_t& r0, uint32_t& r1, uint32_t& r2, uint32_t& r3, uint32_t a) {
    asm volatile("ldmatrix.sync.aligned.m8n8.x4.shared.b16 {%0,%1,%2,%3}, [%4];"
                 : "=r"(r0), "=r"(r1), "=r"(r2), "=r"(r3) : "r"(a));
}
__device__ __forceinline__ void mma_h(float c[4], const uint32_t a[4], const uint32_t b[2]) {
    asm volatile(
        "mma.sync.aligned.m16n8k16.row.col.f32.f16.f16.f32 "
        "{%0,%1,%2,%3}, {%4,%5,%6,%7}, {%8,%9}, {%0,%1,%2,%3};"
        : "+f"(c[0]), "+f"(c[1]), "+f"(c[2]), "+f"(c[3])
        : "r"(a[0]), "r"(a[1]), "r"(a[2]), "r"(a[3]), "r"(b[0]), "r"(b[1]));
}
__device__ __forceinline__ void cp16(uint32_t dst, const void* src) {
    asm volatile("cp.async.cg.shared.global [%0], [%1], 16;" :: "r"(dst), "l"(src));
}
__device__ __forceinline__ void cp_commit() {
    asm volatile("cp.async.commit_group;" ::: "memory");
}
template <int N>
__device__ __forceinline__ void cp_wait() {
    asm volatile("cp.async.wait_group %0;" :: "n"(N) : "memory");
}

// =====================================================================
// fp16 split mma.sync GEMM.  CTA 128(M) x 32*NW2(N), BK=32, NW2*64 thr,
// warps 2(m) x NW2(n), warp tile 64x32.  Operands fp16 planes,
// k-contiguous: A[p][M][lda], B[p][N][ldb].  cp.async 2-stage,
// smem pitch 40 halves -> conflict-free LDSM.
// EPI: 0 fp32+bias, 1 fp16 hi/lo out+bias, 2 exp->P + col-Z atomics,
//      3 fp32 store into split-K partial buffer, 4 QKV scatter,
//      5 fp16 hi-only out+bias(+relu)
// ANP: A planes (2 split, 1 single).  MMAs/step = ANP + 1.
// =====================================================================
template <int EPI, int ANP, int RELU, int SKBITS, int NW2>
__global__ void __launch_bounds__(NW2 * 64, (NW2 == 2) ? 3 : 2)
gg(const __half* __restrict__ A, const __half* __restrict__ B,
   const float* __restrict__ bias, const float* __restrict__ bias2,
   const float* __restrict__ bias3, void* __restrict__ Cv,
   float* __restrict__ Zb,
   int K, int lda, int ldb, int ldc,
   size_t aZ, size_t bZ, size_t cZ, size_t pA, size_t pB, size_t pC,
   float scale)
{
    constexpr int T     = NW2 * 64;
    constexpr int BNT   = 32 * NW2;
    constexpr int ASEG_ = 10240;          // 128 rows * 80B
    constexpr int BSEG_ = BNT * 80;
    constexpr int STG   = ANP * ASEG_ + 2 * BSEG_;
    constexpr int CA    = 512 / T;        // A 16B-chunks per thread per plane

    extern __shared__ __align__(16) unsigned char sm[];
    const uint32_t smb = (uint32_t)__cvta_generic_to_shared(sm);

    const int tid = threadIdx.x;
    const int warp = tid >> 5, lane = tid & 31;
    const int g = lane >> 2, tg = lane & 3;
    const int b3 = (lane >> 3) & 1, b4 = (lane >> 4) & 1;
    const int m0 = (warp & 1) * 64, n0 = (warp >> 1) * 32;

    const int z = blockIdx.z;
    const int zhead = z >> SKBITS;
    const int ksplit = z & ((1 << SKBITS) - 1);
    const int bm = blockIdx.y * 128;
    const int bn = blockIdx.x * BNT;

    const __half* Ag = A + zhead * aZ + (size_t)ksplit * K;
    const __half* Bg = B + zhead * bZ + (size_t)ksplit * K;

    uint32_t aOff[4], bOff[2];
    #pragma unroll
    for (int tm = 0; tm < 4; tm++)
        aOff[tm] = ((m0 + tm * 16 + (lane & 7) + b3 * 8) * 40 + b4 * 8) * 2;
    #pragma unroll
    for (int q = 0; q < 2; q++)
        bOff[q] = ((n0 + q * 16 + (lane & 7) + b4 * 8) * 40 + b3 * 8) * 2;

    auto ldgsts = [&](int st, int slab) {
        const int k0 = slab << 5;
        #pragma unroll
        for (int p = 0; p < ANP; p++)
            #pragma unroll
            for (int j = 0; j < CA; j++) {
                int idx = tid + j * T;
                int row = idx >> 2, kc = idx & 3;
                cp16(smb + st * STG + p * ASEG_ + row * 80 + kc * 16,
                     Ag + p * pA + (size_t)(bm + row) * lda + k0 + kc * 8);
            }
        #pragma unroll
        for (int p = 0; p < 2; p++)
            #pragma unroll
            for (int j = 0; j < 2; j++) {
                int idx = tid + j * T;
                int row = idx >> 2, kc = idx & 3;
                cp16(smb + st * STG + ANP * ASEG_ + p * BSEG_ + row * 80 + kc * 16,
                     Bg + p * pB + (size_t)(bn + row) * ldb + k0 + kc * 8);
            }
        cp_commit();
    };

    float acc[4][4][4];
    #pragma unroll
    for (int tm = 0; tm < 4; tm++)
        #pragma unroll
        for (int tn = 0; tn < 4; tn++)
            #pragma unroll
            for (int r = 0; r < 4; r++) acc[tm][tn][r] = 0.f;

    const int ns = K >> 5;
    ldgsts(0, 0);
    ldgsts(1, 1);
    cp_wait<1>();
    __syncthreads();

    for (int i = 0; i < ns; i++) {
        const int buf = i & 1;
        const uint32_t aB = smb + buf * STG;
        const uint32_t bB = smb + buf * STG + ANP * ASEG_;
        #pragma unroll
        for (int ks = 0; ks < 2; ks++) {
            uint32_t af[4][2][4], bf[2][4][2];
            #pragma unroll
            for (int tm = 0; tm < 4; tm++)
                #pragma unroll
                for (int p = 0; p < ANP; p++)
                    ldsm4(af[tm][p][0], af[tm][p][1], af[tm][p][2], af[tm][p][3],
                          aB + p * ASEG_ + aOff[tm] + ks * 32);
            #pragma unroll
            for (int p = 0; p < 2; p++)
                #pragma unroll
                for (int q = 0; q < 2; q++) {
                    uint32_t r0, r1, r2, r3;
                    ldsm4(r0, r1, r2, r3, bB + p * BSEG_ + bOff[q] + ks * 32);
                    bf[p][q * 2 + 0][0] = r0; bf[p][q * 2 + 0][1] = r1;
                    bf[p][q * 2 + 1][0] = r2; bf[p][q * 2 + 1][1] = r3;
                }
            #pragma unroll
            for (int tm = 0; tm < 4; tm++)
                #pragma unroll
                for (int tn = 0; tn < 4; tn++) {
                    mma_h(acc[tm][tn], af[tm][0], bf[0][tn]);
                    mma_h(acc[tm][tn], af[tm][0], bf[1][tn]);
                    if (ANP == 2) mma_h(acc[tm][tn], af[tm][1], bf[0][tn]);
                }
        }
        __syncthreads();
        if (i + 2 < ns) ldgsts(buf, i + 2);
        if (i + 1 < ns) {
            if (i + 2 < ns) cp_wait<1>(); else cp_wait<0>();
            __syncthreads();
        }
    }

    // ------------------ epilogues ------------------
    if (EPI == 2) {
        __half* Pz = (__half*)Cv + zhead * cZ;
        float cs[4][2];
        #pragma unroll
        for (int tn = 0; tn < 4; tn++) { cs[tn][0] = 0.f; cs[tn][1] = 0.f; }
        #pragma unroll
        for (int tm = 0; tm < 4; tm++)
            #pragma unroll
            for (int half = 0; half < 2; half++) {
                const int row = bm + m0 + tm * 16 + g + half * 8;
                #pragma unroll
                for (int tn = 0; tn < 4; tn++) {
                    float px = __expf(acc[tm][tn][half * 2 + 0] * scale);
                    float py = __expf(acc[tm][tn][half * 2 + 1] * scale);
                    cs[tn][0] += px; cs[tn][1] += py;
                    *(uint32_t*)(Pz + (size_t)row * ldc + bn + n0 + tn * 8 + 2 * tg) =
                        pkh(__float2half_rn(px), __float2half_rn(py));
                }
            }
        float* Zp = Zb + (size_t)zhead * SEQ;
        #pragma unroll
        for (int tn = 0; tn < 4; tn++)
            #pragma unroll
            for (int j = 0; j < 2; j++) {
                float v = cs[tn][j];
                v += __shfl_xor_sync(0xffffffffu, v, 4);
                v += __shfl_xor_sync(0xffffffffu, v, 8);
                v += __shfl_xor_sync(0xffffffffu, v, 16);
                if (lane < 4) atomicAdd(Zp + bn + n0 + tn * 8 + 2 * tg + j, v);
            }
    } else if (EPI == 3) {
        float* C = (float*)Cv + (size_t)ksplit * SEQ * DM + (size_t)zhead * 64;
        #pragma unroll
        for (int tm = 0; tm < 4; tm++)
            #pragma unroll
            for (int half = 0; half < 2; half++) {
                const int row = bm + m0 + tm * 16 + g + half * 8;
                #pragma unroll
                for (int tn = 0; tn < 4; tn++) {
                    const int nc = n0 + tn * 8 + 2 * tg;
                    *(float2*)(C + (size_t)row * DM + nc) =
                        make_float2(acc[tm][tn][half * 2 + 0], acc[tm][tn][half * 2 + 1]);
                }
            }
    } else if (EPI == 4) {
        #pragma unroll
        for (int tn = 0; tn < 4; tn++) {
            const int eg  = bn + n0 + tn * 8 + 2 * tg;
            const int seg = eg >> 10;
            const int hh  = (eg >> 6) & 15;
            const int e   = eg & 63;
            const float* bsel = (seg == 0) ? bias : (seg == 1) ? bias2 : bias3;
            float2 bb = *(const float2*)(bsel + hh * 64 + e);
            #pragma unroll
            for (int tm = 0; tm < 4; tm++)
                #pragma unroll
                for (int half = 0; half < 2; half++) {
                    const int row = bm + m0 + tm * 16 + g + half * 8;
                    float vx = acc[tm][tn][half * 2 + 0] + bb.x;
                    float vy = acc[tm][tn][half * 2 + 1] + bb.y;
                    if (seg == 2) {
                        *(float2*)(g_Vf + ((size_t)hh * SEQ + row) * HDIM + e) =
                            make_float2(vx, vy);
                    } else {
                        __half hx, lx, hy, ly;
                        split_h(vx, hx, lx); split_h(vy, hy, ly);
                        __half* O = (seg == 0) ? g_Qsp : g_Ksp;
                        size_t base = (size_t)hh * 2 * SEQ * HDIM + (size_t)row * HDIM + e;
                        *(uint32_t*)(O + base)                      = pkh(hx, hy);
                        *(uint32_t*)(O + base + (size_t)SEQ * HDIM) = pkh(lx, ly);
                    }
                }
        }
    } else if (EPI == 1 || EPI == 5) {
        __half* Ch = (__half*)Cv + zhead * cZ;
        __half* Cl = Ch + pC;
        #pragma unroll
        for (int tn = 0; tn < 4; tn++) {
            const int col = bn + n0 + tn * 8 + 2 * tg;
            float2 bb = *(const float2*)(bias + col);
            #pragma unroll
            for (int tm = 0; tm < 4; tm++)
                #pragma unroll
                for (int half = 0; half < 2; half++) {
                    const int row = bm + m0 + tm * 16 + g + half * 8;
                    float vx = acc[tm][tn][half * 2 + 0] + bb.x;
                    float vy = acc[tm][tn][half * 2 + 1] + bb.y;
                    if (RELU) { vx = fmaxf(vx, 0.f); vy = fmaxf(vy, 0.f); }
                    size_t o = (size_t)row * ldc + col;
                    if (EPI == 5) {
                        *(uint32_t*)(Ch + o) = pkh(__float2half_rn(vx), __float2half_rn(vy));
                    } else {
                        __half hx, lx, hy, ly;
                        split_h(vx, hx, lx); split_h(vy, hy, ly);
                        *(uint32_t*)(Ch + o) = pkh(hx, hy);
                        *(uint32_t*)(Cl + o) = pkh(lx, ly);
                    }
                }
        }
    } else {
        float* C = (float*)Cv + zhead * cZ;
        #pragma unroll
        for (int tn = 0; tn < 4; tn++) {
            const int col = bn + n0 + tn * 8 + 2 * tg;
            float2 bb = *(const float2*)(bias + col);
            #pragma unroll
            for (int tm = 0; tm < 4; tm++)
                #pragma unroll
                for (int half = 0; half < 2; half++) {
                    const int row = bm + m0 + tm * 16 + g + half * 8;
                    *(float2*)(C + (size_t)row * ldc + col) =
                        make_float2(acc[tm][tn][half * 2 + 0] + bb.x,
                                    acc[tm][tn][half * 2 + 1] + bb.y);
                }
        }
    }
}

// =====================================================================
// prep / glue kernels
// =====================================================================
__global__ void splitf(const float* __restrict__ in, __half* __restrict__ out, size_t n)
{
    size_t i = (size_t)blockIdx.x * blockDim.x + threadIdx.x;
    if (i < n) {
        __half h, l;
        split_h(in[i], h, l);
        out[i] = h; out[n + i] = l;
    }
}

__global__ void tspw(const float* __restrict__ W, __half* __restrict__ O,
                     int K, int N, size_t plane, int rowOff, int zstep)
{
    __shared__ float t[32][33];
    const int z = blockIdx.z;
    const int n0 = blockIdx.x * 32, k0 = blockIdx.y * 32;
    const int tx = threadIdx.x, ty = threadIdx.y;
    const float* Wb = W + (size_t)z * K * N;
    #pragma unroll
    for (int i = 0; i < 32; i += 8)
        t[ty + i][tx] = Wb[(size_t)(k0 + ty + i) * N + n0 + tx];
    __syncthreads();
    #pragma unroll
    for (int i = 0; i < 32; i += 8) {
        __half h, l;
        split_h(t[tx][ty + i], h, l);
        size_t o = (size_t)(rowOff + z * zstep + n0 + ty + i) * K + k0 + tx;
        O[o] = h; O[plane + o] = l;
    }
}

__global__ void rescaleV(const float* __restrict__ Vf, const float* __restrict__ Zi,
                         __half* __restrict__ Vn)
{
    __shared__ float t[32][33];
    const int h = blockIdx.z;
    const int e0 = blockIdx.x * 32, s0 = blockIdx.y * 32;
    const int tx = threadIdx.x, ty = threadIdx.y;
    const float* Vb = Vf + (size_t)h * SEQ * HDIM;
    const float* Zp = Zi + (size_t)h * SEQ;
    #pragma unroll
    for (int i = 0; i < 32; i += 8) {
        int s = s0 + ty + i;
        t[ty + i][tx] = Vb[(size_t)s * HDIM + e0 + tx] * Zp[s];
    }
    __syncthreads();
    __half* Ob = Vn + (size_t)h * 2 * HDIM * SEQ;
    #pragma unroll
    for (int i = 0; i < 32; i += 8) {
        __half hv, lv;
        split_h(t[tx][ty + i], hv, lv);
        size_t o = (size_t)(e0 + ty + i) * SEQ + s0 + tx;
        Ob[o] = hv; Ob[(size_t)HDIM * SEQ + o] = lv;
    }
}

// Csp = split(c0 + c1)
__global__ void reduce2split(const float* __restrict__ c0, __half* __restrict__ out, size_t n)
{
    size_t i = (size_t)blockIdx.x * blockDim.x + threadIdx.x;
    if (i < n) {
        float s = c0[i] + c0[n + i];
        __half h, l;
        split_h(s, h, l);
        out[i] = h; out[n + i] = l;
    }
}

__global__ void zerok(float* __restrict__ p, int n)
{
    int i = blockIdx.x * blockDim.x + threadIdx.x;
    if (i < n) p[i] = 0.f;
}
__global__ void recipk(const float* __restrict__ a, float* __restrict__ b, int n)
{
    int i = blockIdx.x * blockDim.x + threadIdx.x;
    if (i < n) b[i] = 1.f / a[i];
}

// =====================================================================
extern "C" void kernel_launch(void* const* d_in, const int* in_sizes, int n_in,
                              void* d_out, int out_size)
{
    const float* x  = (const float*)d_in[0];
    const float* Wq = (const float*)d_in[1];
    const float* bq = (const float*)d_in[2];
    const float* Wk = (const float*)d_in[3];
    const float* bk = (const float*)d_in[4];
    const float* Wv = (const float*)d_in[5];
    const float* bv = (const float*)d_in[6];
    const float* Wp = (const float*)d_in[7];
    const float* bp = (const float*)d_in[8];
    const float* W1 = (const float*)d_in[9];
    const float* b1 = (const float*)d_in[10];
    const float* W2 = (const float*)d_in[11];
    const float* b2 = (const float*)d_in[12];
    float* out = (float*)d_out;

    __half *Xsp, *Wqkvt, *Wpt, *W1t, *W2t, *Qsp, *Ksp, *Vn, *P, *Csp, *Projsp, *Hsp;
    float *Vf, *Z, *Zinv, *cpart;
    cudaGetSymbolAddress((void**)&Xsp,    g_Xsp);
    cudaGetSymbolAddress((void**)&Wqkvt,  g_Wqkvt);
    cudaGetSymbolAddress((void**)&Wpt,    g_Wpt);
    cudaGetSymbolAddress((void**)&W1t,    g_W1t);
    cudaGetSymbolAddress((void**)&W2t,    g_W2t);
    cudaGetSymbolAddress((void**)&Qsp,    g_Qsp);
    cudaGetSymbolAddress((void**)&Ksp,    g_Ksp);
    cudaGetSymbolAddress((void**)&Vf,     g_Vf);
    cudaGetSymbolAddress((void**)&Vn,     g_Vn);
    cudaGetSymbolAddress((void**)&P,      g_P);
    cudaGetSymbolAddress((void**)&Z,      g_Z);
    cudaGetSymbolAddress((void**)&Zinv,   g_Zinv);
    cudaGetSymbolAddress((void**)&cpart,  g_cpart);
    cudaGetSymbolAddress((void**)&Csp,    g_Csp);
    cudaGetSymbolAddress((void**)&Projsp, g_Projsp);
    cudaGetSymbolAddress((void**)&Hsp,    g_Hsp);

    const int SM_A2 = 2 * (2 * 10240 + 2 * 128 * 80);  // 81920
    const int SM_A1 = 2 * (1 * 10240 + 2 * 128 * 80);  // 61440
    const int SM_AV = 2 * (1 * 10240 + 2 * 64 * 80);   // 40960
    cudaFuncSetAttribute(gg<4,2,0,0,4>, cudaFuncAttributeMaxDynamicSharedMemorySize, SM_A2);
    cudaFuncSetAttribute(gg<2,1,0,0,4>, cudaFuncAttributeMaxDynamicSharedMemorySize, SM_A1);
    cudaFuncSetAttribute(gg<3,1,0,1,2>, cudaFuncAttributeMaxDynamicSharedMemorySize, SM_AV);
    cudaFuncSetAttribute(gg<1,2,0,0,4>, cudaFuncAttributeMaxDynamicSharedMemorySize, SM_A2);
    cudaFuncSetAttribute(gg<5,2,1,0,4>, cudaFuncAttributeMaxDynamicSharedMemorySize, SM_A2);
    cudaFuncSetAttribute(gg<0,1,0,0,4>, cudaFuncAttributeMaxDynamicSharedMemorySize, SM_A1);

    dim3 tb(32, 8);
    // prep
    splitf<<<(SEQ * DM + 255) / 256, 256>>>(x, Xsp, (size_t)SEQ * DM);
    tspw<<<dim3(2, 32, NH), tb>>>(Wq, Wqkvt, DM, HDIM, (size_t)NQKV * DM, 0,    64);
    tspw<<<dim3(2, 32, NH), tb>>>(Wk, Wqkvt, DM, HDIM, (size_t)NQKV * DM, 1024, 64);
    tspw<<<dim3(2, 32, NH), tb>>>(Wv, Wqkvt, DM, HDIM, (size_t)NQKV * DM, 2048, 64);
    tspw<<<dim3(32, 32, 1),  tb>>>(Wp, Wpt, DM, DM,  (size_t)DM * DM,  0, 0);
    tspw<<<dim3(128, 32, 1), tb>>>(W1, W1t, DM, FFD, (size_t)FFD * DM, 0, 0);
    tspw<<<dim3(32, 128, 1), tb>>>(W2, W2t, FFD, DM, (size_t)DM * FFD, 0, 0);
    zerok<<<(NH * SEQ + 255) / 256, 256>>>(Z, NH * SEQ);

    // 1) fused QKV
    gg<4,2,0,0,4><<<dim3(NQKV / 128, SEQ / 128, 1), 256, SM_A2>>>(
        Xsp, Wqkvt, bq, bk, bv, nullptr, nullptr,
        DM, DM, DM, 0, 0, 0, 0, (size_t)SEQ * DM, (size_t)NQKV * DM, 0, 1.f);

    // 2) P = exp(K.Q/8); Z column sums   (K hi-plane only: 2 MMAs)
    gg<2,1,0,0,4><<<dim3(SEQ / 128, SEQ / 128, NH), 256, SM_A1>>>(
        Ksp, Qsp, nullptr, nullptr, nullptr, P, Z,
        HDIM, HDIM, HDIM, SEQ,
        (size_t)2 * SEQ * HDIM, (size_t)2 * SEQ * HDIM, (size_t)SEQ * SEQ,
        0, (size_t)SEQ * HDIM, 0, 0.125f);

    // 3) Zinv; Vn = split(V/Z) transposed
    recipk<<<(NH * SEQ + 255) / 256, 256>>>(Z, Zinv, NH * SEQ);
    rescaleV<<<dim3(2, 64, NH), tb>>>(Vf, Zinv, Vn);

    // 4) AV split-K=2 into private partials (no atomics)
    gg<3,1,0,1,2><<<dim3(1, SEQ / 128, NH * 2), 128, SM_AV>>>(
        P, Vn, nullptr, nullptr, nullptr, cpart, nullptr,
        SEQ / 2, SEQ, SEQ, DM,
        (size_t)SEQ * SEQ, (size_t)2 * HDIM * SEQ, 0,
        0, (size_t)HDIM * SEQ, 0, 1.f);

    // 5) Csp = split(cpart0 + cpart1)
    reduce2split<<<(SEQ * DM + 255) / 256, 256>>>(cpart, Csp, (size_t)SEQ * DM);

    // 6) proj = concat @ Wp + bp  (fp16 split out)
    gg<1,2,0,0,4><<<dim3(DM / 128, SEQ / 128, 1), 256, SM_A2>>>(
        Csp, Wpt, bp, nullptr, nullptr, Projsp, nullptr,
        DM, DM, DM, DM, 0, 0, 0,
        (size_t)SEQ * DM, (size_t)DM * DM, (size_t)SEQ * DM, 1.f);

    // 7) hidden = relu(proj @ W1 + b1)  (fp16 hi-only out)
    gg<5,2,1,0,4><<<dim3(FFD / 128, SEQ / 128, 1), 256, SM_A2>>>(
        Projsp, W1t, b1, nullptr, nullptr, Hsp, nullptr,
        DM, DM, DM, FFD, 0, 0, 0,
        (size_t)SEQ * DM, (size_t)FFD * DM, 0, 1.f);

    // 8) out = hidden @ W2 + b2  (hidden hi-only: 2 MMAs)
    gg<0,1,0,0,4><<<dim3(DM / 128, SEQ / 128, 1), 256, SM_A1>>>(
        Hsp, W2t, b2, nullptr, nullptr, out, nullptr,
        FFD, FFD, FFD, DM, 0, 0, 0,
        0, (size_t)DM * FFD, 0, 1.f);
}